// round 10
// baseline (speedup 1.0000x reference)
#include <cuda_runtime.h>
#include <cuda_bf16.h>
#include <math.h>
#include <stdint.h>

#define MAX_N 2048
#define MAX_E 32768
#define RFANf   0.14433756729740643f  // 1/sqrt(48)
#define RSQRT3f 0.57735026918962576f
#define RS32f   0.17677669529663687f  // 1/sqrt(32)

__device__ float d_q0g[MAX_N*32];
__device__ float d_q1g[MAX_N*48];
__device__ float d_v0e[(size_t)MAX_E*32];
__device__ float d_v1e[(size_t)MAX_E*48];
__device__ float d_logits[MAX_E*4];
__device__ float d_exb[MAX_E*4];
__device__ float d_segmax[MAX_N*4];
__device__ float d_denom[MAX_N*4];
__device__ float d_agg0[MAX_N*32];
__device__ float d_agg1[MAX_N*48];
// W2 bf16 hi/lo, k-pair interleaved: row = set*64 + (lo?32:0) + kp, 2304 words/row
__device__ unsigned int d_W2p[128*2304];

__device__ __forceinline__ void atomicMaxF(float* a, float v){
  if (v >= 0.f) atomicMax((int*)a, __float_as_int(v));
  else atomicMin((unsigned int*)a, __float_as_uint(v));
}
__device__ __forceinline__ unsigned packbf(float x, float y){
  unsigned short ux = __bfloat16_as_ushort(__float2bfloat16(x));
  unsigned short uy = __bfloat16_as_ushort(__float2bfloat16(y));
  return ((unsigned)uy << 16) | (unsigned)ux;
}

__global__ void k_prep(const float* __restrict__ W2k, const float* __restrict__ W2v){
  int t = blockIdx.x*blockDim.x + threadIdx.x;
  if (t >= 2*32*2304) return;
  int s  = t / (32*2304);
  int r  = t - s*32*2304;
  int kp = r / 2304;
  int j  = r - kp*2304;
  const float* W = s ? W2v : W2k;
  float a0 = W[(2*kp)*2304 + j];
  float a1 = W[(2*kp+1)*2304 + j];
  __nv_bfloat16 h0 = __float2bfloat16(a0);
  __nv_bfloat16 h1 = __float2bfloat16(a1);
  d_W2p[(size_t)(s*64 + kp)*2304 + j]      = ((unsigned)__bfloat16_as_ushort(h1)<<16) | __bfloat16_as_ushort(h0);
  d_W2p[(size_t)(s*64 + 32 + kp)*2304 + j] = packbf(a0 - __bfloat162float(h0), a1 - __bfloat162float(h1));
}

__global__ void k_init(int N){
  int t = blockIdx.x*blockDim.x+threadIdx.x;
  if (t < N*4){ d_segmax[t] = -10.0f; d_denom[t] = 0.0f; }
  if (t < N*32) d_agg0[t] = 0.0f;
  if (t < N*48) d_agg1[t] = 0.0f;
}

__global__ void k_q(const float* __restrict__ nf, const float* __restrict__ Wq0,
                    const float* __restrict__ Wq1, int N){
  int t = blockIdx.x*blockDim.x+threadIdx.x;
  if (t >= N*80) return;
  int n = t/80, r = t - n*80;
  if (r < 32){
    int h = r>>3, w = r&7;
    const float* s = nf + (size_t)n*80;
    float acc = 0.f;
#pragma unroll
    for (int u = 0; u < 32; u++) acc += s[u]*Wq0[h*256+u*8+w];
    d_q0g[n*32+r] = acc*RS32f;
  } else {
    int rr = r-32, h = rr/12, q = rr - h*12, w = q/3, i = q - w*3;
    const float* v = nf + (size_t)n*80 + 32;
    float acc = 0.f;
#pragma unroll
    for (int u = 0; u < 16; u++) acc += v[u*3+i]*Wq1[h*64+u*4+w];
    d_q1g[n*48+rr] = acc*0.25f;
  }
}

// ---- smem layout (32-bit words), 32 edges/CTA, 4 CTAs/SM ----
#define OFF_B    0        // 64 rows * 72 (single buffer; also W1 staging in set-setup)
#define BRS      72
#define OFF_U    4608     // union: sA(32*64=2048) | sWT(32*72=2304)
#define ARS      64
#define WTP      72
#define OFF_O0   6912     // 32*32
#define OFF_S1   7936     // 32*16
#define OFF_V1   8448     // 32*48
#define OFF_SS   9984     // 32*32
#define OFF_VV   11008    // 32*48
#define OFF_CVV  12544    // 32*16
#define OFF_SH   13056    // 32*4
#define OFF_EMB  13184    // 32*16
#define OFF_IDX  13696    // 64
#define SMEM_WORDS 13760
#define SMEM_BYTES (SMEM_WORDS*4)   // 55040

__device__ __forceinline__ void cp16(void* dst, const void* src){
  uint32_t a = (uint32_t)__cvta_generic_to_shared(dst);
  asm volatile("cp.async.cg.shared.global [%0], [%1], 16;" :: "r"(a), "l"(src));
}
__device__ __forceinline__ void mma16(float* c, unsigned a0, unsigned a1, unsigned a2, unsigned a3,
                                      unsigned b0, unsigned b1){
  asm volatile(
    "mma.sync.aligned.m16n8k16.row.col.f32.bf16.bf16.f32 "
    "{%0,%1,%2,%3},{%4,%5,%6,%7},{%8,%9},{%0,%1,%2,%3};"
    : "+f"(c[0]), "+f"(c[1]), "+f"(c[2]), "+f"(c[3])
    : "r"(a0), "r"(a1), "r"(a2), "r"(a3), "r"(b0), "r"(b1));
}

__global__ void __launch_bounds__(256,4) k_edge(
    const float* __restrict__ nf, const int* __restrict__ ei,
    const float* __restrict__ esh, const float* __restrict__ emb,
    const float* __restrict__ W1k, const float* __restrict__ b1k,
    const float* __restrict__ b2k,
    const float* __restrict__ W1v, const float* __restrict__ b1v,
    const float* __restrict__ b2v,
    const float* __restrict__ Wd0, const float* __restrict__ Wd1,
    int N, int E)
{
  extern __shared__ float sm[];
  unsigned* sB  = (unsigned*)(sm + OFF_B);
  float* sW1  = sm + OFF_B;                  // alias: W1 staging (set-setup only)
  unsigned* sA  = (unsigned*)(sm + OFF_U);   // alias with sWT (disjoint lifetime)
  float* sWT  = sm + OFF_U;
  float* sO0  = sm + OFF_O0;
  float* sS1  = sm + OFF_S1;
  float* sV1  = sm + OFF_V1;
  float* sSS  = sm + OFF_SS;
  float* sVV  = sm + OFF_VV;
  float* sCVV = sm + OFF_CVV;
  float* sSH  = sm + OFF_SH;
  float* sEmb = sm + OFF_EMB;
  int*   sIdx = (int*)(sm + OFF_IDX);

  const int t    = threadIdx.x;
  const int lane = t & 31;
  const int wid  = t >> 5;
  const int wm   = wid >> 2, wn = wid & 3;   // warp: m16 (wm) x n16 (wn)
  const int g    = lane >> 2, c = lane & 3;
  const int rowA = (wm << 4) + g;
  const int nT   = (E + 31) >> 5;

  for (int et = blockIdx.x; et < nT; et += gridDim.x){
    const int eg0 = et << 5;
    __syncthreads();   // previous iteration fully done

    if (t < 64){
      int e = t & 31, which = t >> 5;
      int eg = eg0 + e;
      sIdx[t] = (eg < E) ? ei[(size_t)which*E + eg] : 0;
    }
    if (t < 128){
      int e = t >> 2, cc = t & 3;
      int eg = eg0 + e;
      bool val = eg < E;
      sSH[e*4+cc] = val ? esh[(size_t)eg*4+cc] : 0.f;
      float4 z = make_float4(0,0,0,0);
      float4 d = val ? *(const float4*)(emb + (size_t)eg*16 + cc*4) : z;
      *(float4*)(sEmb + e*16 + cc*4) = d;
    }
    __syncthreads();

    // gather src node features (20 float4 per edge)
#pragma unroll
    for (int ph = 0; ph < 2; ph++){
      int p = t + ph*256;
      int e = p >> 4, f4 = p & 15;
      const float4* row = (const float4*)(nf + (size_t)sIdx[e]*80);
      float4 d = row[f4];
      if (f4 < 8) *((float4*)(sSS + e*32) + f4) = d;
      else        *((float4*)(sVV + e*48) + (f4-8)) = d;
    }
    if (t < 128){
      int e = t >> 2, f4 = 16 + (t & 3);
      const float4* row = (const float4*)(nf + (size_t)sIdx[e]*80);
      *((float4*)(sVV + e*48) + (f4-8)) = row[f4];
    }
    __syncthreads();

    // cvv
#pragma unroll
    for (int ph = 0; ph < 2; ph++){
      int p = t + ph*256;
      int e = p >> 4, u = p & 15;
      const float* vv = sVV + e*48 + u*3;
      sCVV[p] = (vv[0]*sSH[e*4+1] + vv[1]*sSH[e*4+2] + vv[2]*sSH[e*4+3]) * RSQRT3f;
    }

    // ---- two sets, sequential; accumulators, A smem, B buffer reused ----
#pragma unroll 1
    for (int s = 0; s < 2; s++){
      if (s == 1){
        // logits from k-set accumulators (before re-zero)
        __syncthreads();
        if (t < 128){
          int e = t >> 2, h = t & 3;
          int eg = eg0 + e;
          int dst = sIdx[32 + e];
          float k0r[8];
#pragma unroll
          for (int w = 0; w < 8; w++) k0r[w] = sO0[e*32 + h*8 + w]*RFANf;
          const float* q0 = d_q0g + dst*32 + h*8;
          float l0 = 0.f;
#pragma unroll
          for (int v = 0; v < 8; v++){
            float tv = 0.f;
#pragma unroll
            for (int u = 0; u < 8; u++) tv += q0[u]*Wd0[u*8+v];
            l0 += tv*k0r[v];
          }
          float k1r[12];
#pragma unroll
          for (int w1 = 0; w1 < 4; w1++)
#pragma unroll
            for (int i = 0; i < 3; i++)
              k1r[w1*3+i] = (sS1[e*16+h*4+w1]*sSH[e*4+1+i] + sV1[e*48+h*12+w1*3+i])*RFANf;
          const float* q1 = d_q1g + dst*48 + h*12;
          float l1 = 0.f;
#pragma unroll
          for (int u = 0; u < 4; u++)
#pragma unroll
            for (int v = 0; v < 4; v++){
              float d3 = q1[u*3]*k1r[v*3] + q1[u*3+1]*k1r[v*3+1] + q1[u*3+2]*k1r[v*3+2];
              l1 += Wd1[u*4 + v]*d3;
            }
          float lg = (l0 + l1*RSQRT3f)*0.025f;
          lg = fminf(fmaxf(lg, -10.f), 10.f);
          if (eg < E){
            d_logits[eg*4 + h] = lg;
            atomicMaxF(d_segmax + dst*4 + h, lg);
          }
        }
      }
      __syncthreads();   // B buffer free (last MMA done), sWT/sA free

      // stage W1/b1 into B-buffer region; zero accumulators
      {
        const float* W1s = s ? W1v : W1k;
        const float* b1s = s ? b1v : b1k;
        for (int i = t; i < 1024; i += 256) sW1[i] = W1s[i];
        if (t < 64) sW1[1024+t] = b1s[t];
        for (int i = t; i < 768; i += 256) *(float4*)(sO0 + i*4) = make_float4(0,0,0,0);
      }
      __syncthreads();

      // hE for this set -> sA (bf16 hi/lo pairs)
      {
        int e = t >> 3, kq = (t & 7) << 3;
        float v[8];
#pragma unroll
        for (int kk = 0; kk < 8; kk++){
          int k = kq + kk;
          float a = sW1[1024 + k];
#pragma unroll
          for (int b = 0; b < 16; b++) a += sEmb[e*16+b]*sW1[b*64+k];
          v[kk] = a/(1.f+expf(-a));
        }
        unsigned* arow = sA + e*ARS + (kq>>1);
#pragma unroll
        for (int p = 0; p < 4; p++){
          float x = v[2*p], y = v[2*p+1];
          __nv_bfloat16 hx = __float2bfloat16(x), hy = __float2bfloat16(y);
          arow[p]      = ((unsigned)__bfloat16_as_ushort(hy)<<16) | __bfloat16_as_ushort(hx);
          arow[32 + p] = packbf(x - __bfloat162float(hx), y - __bfloat162float(hy));
        }
      }
      __syncthreads();   // W1 staging consumed; sA valid

      // prefetch B tile 0 of this set (overwrites W1 staging area)
      {
        int r = t >> 2, part = t & 3;
        const unsigned* gsrc = d_W2p + (size_t)(s*64 + r)*2304;
#pragma unroll
        for (int q = 0; q < 4; q++){
          int jw = (part << 2) + (q << 4);
          cp16(sB + r*BRS + jw, gsrc + jw);
        }
        asm volatile("cp.async.commit_group;");
      }

      // hoist A fragments into registers for the whole set
      unsigned ah[4][4], al[4][4];
      {
        const unsigned* aP  = sA + rowA*ARS;
        const unsigned* aP8 = sA + (rowA+8)*ARS;
#pragma unroll
        for (int ks = 0; ks < 4; ks++){
          int kb = ks*8 + c;
          ah[ks][0] = aP[kb];    ah[ks][1] = aP8[kb];
          ah[ks][2] = aP[kb+4];  ah[ks][3] = aP8[kb+4];
          al[ks][0] = aP[32+kb]; al[ks][1] = aP8[32+kb];
          al[ks][2] = aP[32+kb+4]; al[ks][3] = aP8[32+kb+4];
        }
      }
      asm volatile("cp.async.wait_group 0;");
      __syncthreads();   // sA dead (sWT writable); B tile 0 visible

      // ---- 36 tiles of 64 j, single-buffered B (R8 pattern) ----
      int h = 0, off0 = 0;
      for (int it = 0; it < 36; it++){
        int j0 = it << 6;

        // MMA m16 x n16 per warp, bias init
        float acc[2][4];
        {
          const float* b2p = s ? b2v : b2k;
#pragma unroll
          for (int nt = 0; nt < 2; nt++){
            float2 bb = *(const float2*)(b2p + j0 + (wn<<4) + (nt<<3) + 2*c);
            acc[nt][0] = bb.x; acc[nt][1] = bb.y; acc[nt][2] = bb.x; acc[nt][3] = bb.y;
          }
        }
#pragma unroll
        for (int ks = 0; ks < 4; ks++){
          int kb = ks*8 + c;
#pragma unroll
          for (int nt = 0; nt < 2; nt++){
            const unsigned* bP = sB + kb*BRS + (wn<<4) + (nt<<3) + g;
            unsigned bh0 = bP[0],      bh1 = bP[4*BRS];
            unsigned bl0 = bP[32*BRS], bl1 = bP[36*BRS];
            mma16(acc[nt], ah[ks][0],ah[ks][1],ah[ks][2],ah[ks][3], bh0,bh1);
            mma16(acc[nt], al[ks][0],al[ks][1],al[ks][2],al[ks][3], bh0,bh1);
            mma16(acc[nt], ah[ks][0],ah[ks][1],ah[ks][2],ah[ks][3], bl0,bl1);
          }
        }
        // stage w tile
#pragma unroll
        for (int nt = 0; nt < 2; nt++){
          int jl = (wn<<4) + (nt<<3) + 2*c;
          *(float2*)(sWT + rowA*WTP + jl)     = make_float2(acc[nt][0], acc[nt][1]);
          *(float2*)(sWT + (rowA+8)*WTP + jl) = make_float2(acc[nt][2], acc[nt][3]);
        }
        __syncthreads();   // sWT staged; sB consumed by all warps

        // prefetch next B tile (overlaps epilogue)
        if (it + 1 < 36){
          int j02 = (it+1) << 6;
          int r = t >> 2, part = t & 3;
          const unsigned* gsrc = d_W2p + (size_t)(s*64 + r)*2304 + j02;
#pragma unroll
          for (int q = 0; q < 4; q++){
            int jw = (part << 2) + (q << 4);
            cp16(sB + r*BRS + jw, gsrc + jw);
          }
          asm volatile("cp.async.commit_group;");
        }

        // epilogue: contract this 64-j block (h/off0 loop-carried)
        {
          if (off0 < 256){                     // ss -> out0 (coeff ss[u]*sh0)
            int u0 = off0 >> 3;
            int e = t >> 3, ow = t & 7;
            const float* wr = sWT + e*WTP + ow;
            float a = 0.f;
#pragma unroll
            for (int du = 0; du < 8; du++) a += sSS[e*32+u0+du]*wr[du*8];
            sO0[e*32 + h*8 + ow] += a*sSH[e*4];
          } else if (off0 < 384){              // vv -> out0 (coeff cvv[u])
            int u0 = (off0-256) >> 3;
            int e = t >> 3, ow = t & 7;
            const float* wr = sWT + e*WTP + ow;
            float a = 0.f;
#pragma unroll
            for (int du = 0; du < 8; du++) a += sCVV[e*16+u0+du]*wr[du*8];
            sO0[e*32 + h*8 + ow] += a;
          } else if (off0 < 512){              // sv -> s1 (coeff ss[u])
            if (t < 128){
              int u0 = (off0-384) >> 2;
              int e = t >> 2, w1 = t & 3;
              const float* wr = sWT + e*WTP + w1;
              float a = 0.f;
#pragma unroll
              for (int du = 0; du < 16; du++) a += sSS[e*32+u0+du]*wr[du*4];
              sS1[e*16 + h*4 + w1] += a;
            }
          } else {                             // vs -> v1 (coeff vv[u,i]*sh0)
            for (int p = t; p < 384; p += 256){
              int e = p/12, r = p - e*12, w1 = r/3, i = r - w1*3;
              const float* wr = sWT + e*WTP + w1;
              float a = 0.f;
#pragma unroll
              for (int du = 0; du < 16; du++) a += sVV[e*48+du*3+i]*wr[du*4];
              sV1[e*48 + h*12 + w1*3 + i] += a*sSH[e*4];
            }
          }
          off0 += 64;
          if (off0 == 576){ off0 = 0; h++; }
        }
        asm volatile("cp.async.wait_group 0;");
        __syncthreads();   // next B tile visible; epilogue done (sWT reusable)
      }
    }
    __syncthreads();

    // write v-set outputs (accumulators hold set 1 now)
#pragma unroll
    for (int ph = 0; ph < 4; ph++){
      int p = t + ph*256;
      int e = p >> 5, cc = p & 31;
      int eg = eg0 + e;
      if (eg < E) d_v0e[(size_t)eg*32 + cc] = sO0[e*32 + cc]*RFANf;
    }
    for (int p = t; p < 1536; p += 256){
      int e = p/48, r = p - e*48;
      int h = r/12, q = r - h*12, w1 = q/3, i = q - w1*3;
      int eg = eg0 + e;
      if (eg < E)
        d_v1e[(size_t)eg*48 + r] =
          (sS1[e*16 + h*4 + w1]*sSH[e*4+1+i] + sV1[e*48 + r])*RFANf;
    }
  }
}

__global__ void k_ex(const int* __restrict__ ei, int E){
  int t = blockIdx.x*blockDim.x+threadIdx.x;
  if (t >= E*4) return;
  int e = t >> 2, h = t & 3;
  int dst = ei[E + e];
  float ex = expf(d_logits[t] - d_segmax[dst*4+h]);
  d_exb[t] = ex;
  atomicAdd(d_denom + dst*4 + h, ex);
}

__global__ void k_agg(const int* __restrict__ ei, int E){
  int t = blockIdx.x*blockDim.x+threadIdx.x;
  if (t >= E*80) return;
  int e = t/80, r = t - e*80;
  int dst = ei[E + e];
  if (r < 32){
    int h = r >> 3;
    float alpha = d_exb[e*4+h]/(d_denom[dst*4+h] + 1e-12f);
    atomicAdd(d_agg0 + dst*32 + r, alpha*d_v0e[(size_t)e*32 + r]);
  } else {
    int r2 = r - 32, h = r2/12;
    float alpha = d_exb[e*4+h]/(d_denom[dst*4+h] + 1e-12f);
    atomicAdd(d_agg1 + dst*48 + r2, alpha*d_v1e[(size_t)e*48 + r2]);
  }
}

__global__ void k_node(const float* __restrict__ nf,
    const float* __restrict__ Wo0, const float* __restrict__ Wo1,
    const float* __restrict__ Wf10, const float* __restrict__ Wf11,
    const float* __restrict__ Wf20, const float* __restrict__ Wf21,
    float* __restrict__ out, int N)
{
  __shared__ float sx0[32], sx1[48], sa0[64], sa1[48];
  int n = blockIdx.x, t = threadIdx.x;
  if (t < 32){
    float acc = 0.f;
#pragma unroll
    for (int u = 0; u < 32; u++) acc += d_agg0[n*32+u]*Wo0[u*32+t];
    sx0[t] = nf[(size_t)n*80 + t] + acc*RS32f;
  } else if (t < 80){
    int r = t-32, w = r/3, i = r - w*3;
    float acc = 0.f;
#pragma unroll
    for (int u = 0; u < 16; u++) acc += d_agg1[n*48+u*3+i]*Wo1[u*16+w];
    sx1[r] = nf[(size_t)n*80 + 32 + r] + acc*0.25f;
  }
  __syncthreads();
  if (t < 64){
    float acc = 0.f;
#pragma unroll
    for (int u = 0; u < 32; u++) acc += sx0[u]*Wf10[u*64+t];
    float a = acc*RS32f;
    sa0[t] = a/(1.f+expf(-a));
  } else if (t < 112){
    int r = t-64, w = r/3, i = r - w*3;
    float acc = 0.f;
#pragma unroll
    for (int u = 0; u < 16; u++) acc += sx1[u*3+i]*Wf11[u*16+w];
    sa1[r] = acc*0.25f;
  }
  __syncthreads();
  if (t < 16){
    float x = sa1[t*3], y = sa1[t*3+1], z = sa1[t*3+2];
    float nm = sqrtf(x*x+y*y+z*z);
    float g = (nm < 1e-8f) ? 0.f : (nm/(1.f+expf(-nm)))/nm;
    sa1[t*3] = x*g; sa1[t*3+1] = y*g; sa1[t*3+2] = z*g;
  }
  __syncthreads();
  if (t < 32){
    float acc = 0.f;
#pragma unroll
    for (int u = 0; u < 64; u++) acc += sa0[u]*Wf20[u*32+t];
    out[(size_t)n*80 + t] = sx0[t] + acc*0.125f;
  } else if (t < 80){
    int r = t-32, w = r/3, i = r - w*3;
    float acc = 0.f;
#pragma unroll
    for (int u = 0; u < 16; u++) acc += sa1[u*3+i]*Wf21[u*16+w];
    out[(size_t)n*80 + t] = sx1[r] + acc*0.25f;
  }
}

extern "C" void kernel_launch(void* const* d_in, const int* in_sizes, int n_in,
                              void* d_out, int out_size){
  const float* nf   = (const float*)d_in[0];
  const int*   ei   = (const int*)  d_in[1];
  const float* esh  = (const float*)d_in[2];
  const float* emb  = (const float*)d_in[3];
  const float* Wq0  = (const float*)d_in[4];
  const float* Wq1  = (const float*)d_in[5];
  const float* Wk1  = (const float*)d_in[6];
  const float* bk1  = (const float*)d_in[7];
  const float* Wk2  = (const float*)d_in[8];
  const float* bk2  = (const float*)d_in[9];
  const float* Wv1  = (const float*)d_in[10];
  const float* bv1  = (const float*)d_in[11];
  const float* Wv2  = (const float*)d_in[12];
  const float* bv2  = (const float*)d_in[13];
  const float* Wd0  = (const float*)d_in[14];
  const float* Wd1  = (const float*)d_in[15];
  const float* Wo0  = (const float*)d_in[16];
  const float* Wo1  = (const float*)d_in[17];
  const float* Wf10 = (const float*)d_in[18];
  const float* Wf11 = (const float*)d_in[19];
  const float* Wf20 = (const float*)d_in[20];
  const float* Wf21 = (const float*)d_in[21];
  float* out = (float*)d_out;

  int N = in_sizes[0]/80;
  int E = in_sizes[1]/2;

  static int smCount = 0;
  if (!smCount){
    cudaFuncSetAttribute(k_edge, cudaFuncAttributeMaxDynamicSharedMemorySize, SMEM_BYTES);
    cudaDeviceGetAttribute(&smCount, cudaDevAttrMultiProcessorCount, 0);
    if (smCount <= 0) smCount = 148;
  }
  int nT = (E + 31)/32;
  int grid = nT < 4*smCount ? nT : 4*smCount;

  k_prep<<<(2*32*2304+255)/256, 256>>>(Wk2, Wv2);
  k_init<<<(N*48+255)/256, 256>>>(N);
  k_q<<<(N*80+255)/256, 256>>>(nf, Wq0, Wq1, N);
  k_edge<<<grid, 256, SMEM_BYTES>>>(nf, ei, esh, emb,
      Wk1, bk1, bk2, Wv1, bv1, bv2, Wd0, Wd1, N, E);
  k_ex<<<(E*4+255)/256, 256>>>(ei, E);
  k_agg<<<(E*80+255)/256, 256>>>(ei, E);
  k_node<<<N, 128>>>(nf, Wo0, Wo1, Wf10, Wf11, Wf20, Wf21, out, N);
}

// round 11
// speedup vs baseline: 1.4043x; 1.4043x over previous
#include <cuda_runtime.h>
#include <cuda_bf16.h>
#include <math.h>
#include <stdint.h>

#define MAX_N 2048
#define MAX_E 32768
#define RFANf   0.14433756729740643f  // 1/sqrt(48)
#define RSQRT3f 0.57735026918962576f
#define RS32f   0.17677669529663687f  // 1/sqrt(32)

__device__ float d_q0g[MAX_N*32];
__device__ float d_q1g[MAX_N*48];
__device__ float d_v0e[(size_t)MAX_E*32];
__device__ float d_v1e[(size_t)MAX_E*48];
__device__ float d_logits[MAX_E*4];
__device__ float d_exb[MAX_E*4];
__device__ float d_segmax[MAX_N*4];
__device__ float d_denom[MAX_N*4];
__device__ float d_agg0[MAX_N*32];
__device__ float d_agg1[MAX_N*48];
// W2 bf16 hi/lo, k-pair interleaved: row = set*64 + (lo?32:0) + kp, 2304 words/row
__device__ unsigned int d_W2p[128*2304];

__device__ __forceinline__ void atomicMaxF(float* a, float v){
  if (v >= 0.f) atomicMax((int*)a, __float_as_int(v));
  else atomicMin((unsigned int*)a, __float_as_uint(v));
}
__device__ __forceinline__ unsigned packbf(float x, float y){
  unsigned short ux = __bfloat16_as_ushort(__float2bfloat16(x));
  unsigned short uy = __bfloat16_as_ushort(__float2bfloat16(y));
  return ((unsigned)uy << 16) | (unsigned)ux;
}

__global__ void k_prep(const float* __restrict__ W2k, const float* __restrict__ W2v){
  int t = blockIdx.x*blockDim.x + threadIdx.x;
  if (t >= 2*32*2304) return;
  int s  = t / (32*2304);
  int r  = t - s*32*2304;
  int kp = r / 2304;
  int j  = r - kp*2304;
  const float* W = s ? W2v : W2k;
  float a0 = W[(2*kp)*2304 + j];
  float a1 = W[(2*kp+1)*2304 + j];
  __nv_bfloat16 h0 = __float2bfloat16(a0);
  __nv_bfloat16 h1 = __float2bfloat16(a1);
  d_W2p[(size_t)(s*64 + kp)*2304 + j]      = ((unsigned)__bfloat16_as_ushort(h1)<<16) | __bfloat16_as_ushort(h0);
  d_W2p[(size_t)(s*64 + 32 + kp)*2304 + j] = packbf(a0 - __bfloat162float(h0), a1 - __bfloat162float(h1));
}

__global__ void k_init(int N){
  int t = blockIdx.x*blockDim.x+threadIdx.x;
  if (t < N*4){ d_segmax[t] = -10.0f; d_denom[t] = 0.0f; }
  if (t < N*32) d_agg0[t] = 0.0f;
  if (t < N*48) d_agg1[t] = 0.0f;
}

__global__ void k_q(const float* __restrict__ nf, const float* __restrict__ Wq0,
                    const float* __restrict__ Wq1, int N){
  int t = blockIdx.x*blockDim.x+threadIdx.x;
  if (t >= N*80) return;
  int n = t/80, r = t - n*80;
  if (r < 32){
    int h = r>>3, w = r&7;
    const float* s = nf + (size_t)n*80;
    float acc = 0.f;
#pragma unroll
    for (int u = 0; u < 32; u++) acc += s[u]*Wq0[h*256+u*8+w];
    d_q0g[n*32+r] = acc*RS32f;
  } else {
    int rr = r-32, h = rr/12, q = rr - h*12, w = q/3, i = q - w*3;
    const float* v = nf + (size_t)n*80 + 32;
    float acc = 0.f;
#pragma unroll
    for (int u = 0; u < 16; u++) acc += v[u*3+i]*Wq1[h*64+u*4+w];
    d_q1g[n*48+rr] = acc*0.25f;
  }
}

// ---- smem layout (32-bit words), 32 edges/CTA, padded strides ----
#define OFF_A    0        // 32e * 68 (bf16 hi/lo pairs)
#define ARS      68
#define OFF_B    2176     // 64 rows * 72 (single buffer)
#define BRS      72
#define OFF_WT   6784     // 32*72 ; aliased in setup: W1s(1024)+b1s(64)
#define WTP      72
#define OFF_O0   9088     // 32*36 (padded)
#define O0P      36
#define OFF_S1   10240    // 32*20
#define S1P      20
#define OFF_V1   10880    // 32*52
#define V1P      52
#define OFF_SS   12544    // 32*36
#define SSP      36
#define OFF_VV   13696    // 32*52
#define VVP      52
#define OFF_CVV  15360    // 32*20
#define CVP      20
#define OFF_SH   16000    // 32*4
#define OFF_EMB  16128    // 32*16
#define OFF_IDX  16640    // 64
#define SMEM_WORDS 16704
#define SMEM_BYTES (SMEM_WORDS*4)   // 66816

__device__ __forceinline__ void cp16(void* dst, const void* src){
  uint32_t a = (uint32_t)__cvta_generic_to_shared(dst);
  asm volatile("cp.async.cg.shared.global [%0], [%1], 16;" :: "r"(a), "l"(src));
}
__device__ __forceinline__ void mma16(float* c, unsigned a0, unsigned a1, unsigned a2, unsigned a3,
                                      unsigned b0, unsigned b1){
  asm volatile(
    "mma.sync.aligned.m16n8k16.row.col.f32.bf16.bf16.f32 "
    "{%0,%1,%2,%3},{%4,%5,%6,%7},{%8,%9},{%0,%1,%2,%3};"
    : "+f"(c[0]), "+f"(c[1]), "+f"(c[2]), "+f"(c[3])
    : "r"(a0), "r"(a1), "r"(a2), "r"(a3), "r"(b0), "r"(b1));
}

__global__ void __launch_bounds__(256,3) k_edge(
    const float* __restrict__ nf, const int* __restrict__ ei,
    const float* __restrict__ esh, const float* __restrict__ emb,
    const float* __restrict__ W1k, const float* __restrict__ b1k,
    const float* __restrict__ b2k,
    const float* __restrict__ W1v, const float* __restrict__ b1v,
    const float* __restrict__ b2v,
    const float* __restrict__ Wd0, const float* __restrict__ Wd1,
    int N, int E)
{
  extern __shared__ float sm[];
  unsigned* sA  = (unsigned*)(sm + OFF_A);
  unsigned* sB  = (unsigned*)(sm + OFF_B);
  float* sWT  = sm + OFF_WT;
  float* sW1  = sm + OFF_WT;   // alias (set-setup only)
  float* sO0  = sm + OFF_O0;
  float* sS1  = sm + OFF_S1;
  float* sV1  = sm + OFF_V1;
  float* sSS  = sm + OFF_SS;
  float* sVV  = sm + OFF_VV;
  float* sCVV = sm + OFF_CVV;
  float* sSH  = sm + OFF_SH;
  float* sEmb = sm + OFF_EMB;
  int*   sIdx = (int*)(sm + OFF_IDX);

  const int t    = threadIdx.x;
  const int lane = t & 31;
  const int wid  = t >> 5;
  const int wm   = wid >> 2, wn = wid & 3;   // warp: m16 (wm) x n16 (wn)
  const int g    = lane >> 2, c = lane & 3;
  const int rowA = (wm << 4) + g;
  const int nT   = (E + 31) >> 5;

  for (int et = blockIdx.x; et < nT; et += gridDim.x){
    const int eg0 = et << 5;
    __syncthreads();

    // prefetch B chunk 0 (set 0, j0=0)
    {
      int r = t >> 2, part = t & 3;
      const unsigned* gsrc = d_W2p + (size_t)r*2304;
#pragma unroll
      for (int q = 0; q < 4; q++){
        int jw = (part << 2) + (q << 4);
        cp16(sB + r*BRS + jw, gsrc + jw);
      }
      asm volatile("cp.async.commit_group;");
    }

    if (t < 64){
      int e = t & 31, which = t >> 5;
      int eg = eg0 + e;
      sIdx[t] = (eg < E) ? ei[(size_t)which*E + eg] : 0;
    }
    if (t < 128){
      int e = t >> 2, cc = t & 3;
      int eg = eg0 + e;
      bool val = eg < E;
      sSH[e*4+cc] = val ? esh[(size_t)eg*4+cc] : 0.f;
      float4 z = make_float4(0,0,0,0);
      float4 d = val ? *(const float4*)(emb + (size_t)eg*16 + cc*4) : z;
      *(float4*)(sEmb + e*16 + cc*4) = d;
    }
    __syncthreads();

    // gather src node features (20 float4 per edge), padded strides
#pragma unroll
    for (int ph = 0; ph < 2; ph++){
      int p = t + ph*256;
      int e = p >> 4, f4 = p & 15;
      const float4* row = (const float4*)(nf + (size_t)sIdx[e]*80);
      float4 d = row[f4];
      if (f4 < 8) *((float4*)(sSS + e*SSP) + f4) = d;
      else        *((float4*)(sVV + e*VVP) + (f4-8)) = d;
    }
    if (t < 128){
      int e = t >> 2, f4 = 16 + (t & 3);
      const float4* row = (const float4*)(nf + (size_t)sIdx[e]*80);
      *((float4*)(sVV + e*VVP) + (f4-8)) = row[f4];
    }
    __syncthreads();

    // cvv
#pragma unroll
    for (int ph = 0; ph < 2; ph++){
      int p = t + ph*256;
      int e = p >> 4, u = p & 15;
      const float* vv = sVV + e*VVP + u*3;
      sCVV[e*CVP + u] = (vv[0]*sSH[e*4+1] + vv[1]*sSH[e*4+2] + vv[2]*sSH[e*4+3]) * RSQRT3f;
    }
    __syncthreads();

    // ---- two sets, sequential; accumulators + A smem reused ----
#pragma unroll 1
    for (int s = 0; s < 2; s++){
      if (s == 1){
        // logits from k-set accumulators (before re-zero)
        __syncthreads();
        if (t < 128){
          int e = t >> 2, h = t & 3;
          int eg = eg0 + e;
          int dst = sIdx[32 + e];
          float k0r[8];
#pragma unroll
          for (int w = 0; w < 8; w++) k0r[w] = sO0[e*O0P + h*8 + w]*RFANf;
          const float* q0 = d_q0g + dst*32 + h*8;
          float l0 = 0.f;
#pragma unroll
          for (int v = 0; v < 8; v++){
            float tv = 0.f;
#pragma unroll
            for (int u = 0; u < 8; u++) tv += q0[u]*Wd0[u*8+v];
            l0 += tv*k0r[v];
          }
          float k1r[12];
#pragma unroll
          for (int w1 = 0; w1 < 4; w1++)
#pragma unroll
            for (int i = 0; i < 3; i++)
              k1r[w1*3+i] = (sS1[e*S1P+h*4+w1]*sSH[e*4+1+i] + sV1[e*V1P+h*12+w1*3+i])*RFANf;
          const float* q1 = d_q1g + dst*48 + h*12;
          float l1 = 0.f;
#pragma unroll
          for (int u = 0; u < 4; u++)
#pragma unroll
            for (int v = 0; v < 4; v++){
              float d3 = q1[u*3]*k1r[v*3] + q1[u*3+1]*k1r[v*3+1] + q1[u*3+2]*k1r[v*3+2];
              l1 += Wd1[u*4 + v]*d3;
            }
          float lg = (l0 + l1*RSQRT3f)*0.025f;
          lg = fminf(fmaxf(lg, -10.f), 10.f);
          if (eg < E){
            d_logits[eg*4 + h] = lg;
            atomicMaxF(d_segmax + dst*4 + h, lg);
          }
        }
        __syncthreads();
      }

      // stage W1/b1 for this set into sWT alias; zero accumulators (contiguous 3456 w)
      {
        const float* W1s = s ? W1v : W1k;
        const float* b1s = s ? b1v : b1k;
        for (int i = t; i < 1024; i += 256) sW1[i] = W1s[i];
        if (t < 64) sW1[1024+t] = b1s[t];
        for (int i = t; i < 864; i += 256) *(float4*)(sO0 + i*4) = make_float4(0,0,0,0);
      }
      __syncthreads();

      // hE for this set -> sA (bf16 hi/lo pairs)
      {
        int e = t >> 3, kq = (t & 7) << 3;
        float v[8];
#pragma unroll
        for (int kk = 0; kk < 8; kk++){
          int k = kq + kk;
          float a = sW1[1024 + k];
#pragma unroll
          for (int b = 0; b < 16; b++) a += sEmb[e*16+b]*sW1[b*64+k];
          v[kk] = a/(1.f+expf(-a));
        }
        unsigned* arow = sA + e*ARS + (kq>>1);
#pragma unroll
        for (int p = 0; p < 4; p++){
          float x = v[2*p], y = v[2*p+1];
          __nv_bfloat16 hx = __float2bfloat16(x), hy = __float2bfloat16(y);
          arow[p]      = ((unsigned)__bfloat16_as_ushort(hy)<<16) | __bfloat16_as_ushort(hx);
          arow[32 + p] = packbf(x - __bfloat162float(hx), y - __bfloat162float(hy));
        }
      }
      __syncthreads();

      // hoist A fragments into registers for the whole set
      unsigned ah[4][4], al[4][4];
      {
        const unsigned* aP  = sA + rowA*ARS;
        const unsigned* aP8 = sA + (rowA+8)*ARS;
#pragma unroll
        for (int ks = 0; ks < 4; ks++){
          int kb = ks*8 + c;
          ah[ks][0] = aP[kb];    ah[ks][1] = aP8[kb];
          ah[ks][2] = aP[kb+4];  ah[ks][3] = aP8[kb+4];
          al[ks][0] = aP[32+kb]; al[ks][1] = aP8[32+kb];
          al[ks][2] = aP[32+kb+4]; al[ks][3] = aP8[32+kb+4];
        }
      }
      __syncthreads();   // sA dead; sWT may now be written

      // ---- 36 tiles of 64 j ----
      int h = 0, off0 = 0;
      for (int it = 0; it < 36; it++){
        int j0 = it << 6;
        int ct = s*36 + it;

        // MMA m16 x n16 per warp, bias init
        float acc[2][4];
        {
          const float* b2p = s ? b2v : b2k;
#pragma unroll
          for (int nt = 0; nt < 2; nt++){
            float2 bb = *(const float2*)(b2p + j0 + (wn<<4) + (nt<<3) + 2*c);
            acc[nt][0] = bb.x; acc[nt][1] = bb.y; acc[nt][2] = bb.x; acc[nt][3] = bb.y;
          }
        }
#pragma unroll
        for (int ks = 0; ks < 4; ks++){
          int kb = ks*8 + c;
#pragma unroll
          for (int nt = 0; nt < 2; nt++){
            const unsigned* bP = sB + kb*BRS + (wn<<4) + (nt<<3) + g;
            unsigned bh0 = bP[0],      bh1 = bP[4*BRS];
            unsigned bl0 = bP[32*BRS], bl1 = bP[36*BRS];
            mma16(acc[nt], ah[ks][0],ah[ks][1],ah[ks][2],ah[ks][3], bh0,bh1);
            mma16(acc[nt], al[ks][0],al[ks][1],al[ks][2],al[ks][3], bh0,bh1);
            mma16(acc[nt], ah[ks][0],ah[ks][1],ah[ks][2],ah[ks][3], bl0,bl1);
          }
        }
        // stage w tile
#pragma unroll
        for (int nt = 0; nt < 2; nt++){
          int jl = (wn<<4) + (nt<<3) + 2*c;
          *(float2*)(sWT + rowA*WTP + jl)     = make_float2(acc[nt][0], acc[nt][1]);
          *(float2*)(sWT + (rowA+8)*WTP + jl) = make_float2(acc[nt][2], acc[nt][3]);
        }
        __syncthreads();   // sWT staged; sB consumed

        // prefetch next B chunk (overlaps epilogue)
        if (ct + 1 < 72){
          int s2 = (ct+1 >= 36) ? 1 : 0;
          int j02 = ((ct+1) - s2*36) << 6;
          int r = t >> 2, part = t & 3;
          const unsigned* gsrc = d_W2p + (size_t)(s2*64 + r)*2304 + j02;
#pragma unroll
          for (int q = 0; q < 4; q++){
            int jw = (part << 2) + (q << 4);
            cp16(sB + r*BRS + jw, gsrc + jw);
          }
          asm volatile("cp.async.commit_group;");
        }

        // epilogue: contract this 64-j block (h/off0 loop-carried; padded strides)
        {
          if (off0 < 256){                     // ss -> out0 (coeff ss[u]*sh0)
            int u0 = off0 >> 3;
            int e = t >> 3, ow = t & 7;
            const float* wr = sWT + e*WTP + ow;
            float a = 0.f;
#pragma unroll
            for (int du = 0; du < 8; du++) a += sSS[e*SSP+u0+du]*wr[du*8];
            sO0[e*O0P + h*8 + ow] += a*sSH[e*4];
          } else if (off0 < 384){              // vv -> out0 (coeff cvv[u])
            int u0 = (off0-256) >> 3;
            int e = t >> 3, ow = t & 7;
            const float* wr = sWT + e*WTP + ow;
            float a = 0.f;
#pragma unroll
            for (int du = 0; du < 8; du++) a += sCVV[e*CVP+u0+du]*wr[du*8];
            sO0[e*O0P + h*8 + ow] += a;
          } else if (off0 < 512){              // sv -> s1 (coeff ss[u])
            if (t < 128){
              int u0 = (off0-384) >> 2;
              int e = t >> 2, w1 = t & 3;
              const float* wr = sWT + e*WTP + w1;
              float a = 0.f;
#pragma unroll
              for (int du = 0; du < 16; du++) a += sSS[e*SSP+u0+du]*wr[du*4];
              sS1[e*S1P + h*4 + w1] += a;
            }
          } else {                             // vs -> v1 (coeff vv[u,i]*sh0)
            for (int p = t; p < 384; p += 256){
              int e = p/12, r = p - e*12, w1 = r/3, i = r - w1*3;
              const float* wr = sWT + e*WTP + w1;
              float a = 0.f;
#pragma unroll
              for (int du = 0; du < 16; du++) a += sVV[e*VVP+du*3+i]*wr[du*4];
              sV1[e*V1P + h*12 + w1*3 + i] += a*sSH[e*4];
            }
          }
          off0 += 64;
          if (off0 == 576){ off0 = 0; h++; }
        }
        asm volatile("cp.async.wait_group 0;");
        __syncthreads();   // next B visible; epilogue done (sWT reusable)
      }
    }
    __syncthreads();

    // write v-set outputs (accumulators hold set 1 now)
#pragma unroll
    for (int ph = 0; ph < 4; ph++){
      int p = t + ph*256;
      int e = p >> 5, cc = p & 31;
      int eg = eg0 + e;
      if (eg < E) d_v0e[(size_t)eg*32 + cc] = sO0[e*O0P + cc]*RFANf;
    }
    for (int p = t; p < 1536; p += 256){
      int e = p/48, r = p - e*48;
      int h = r/12, q = r - h*12, w1 = q/3, i = q - w1*3;
      int eg = eg0 + e;
      if (eg < E)
        d_v1e[(size_t)eg*48 + r] =
          (sS1[e*S1P + h*4 + w1]*sSH[e*4+1+i] + sV1[e*V1P + r])*RFANf;
    }
  }
}

__global__ void k_ex(const int* __restrict__ ei, int E){
  int t = blockIdx.x*blockDim.x+threadIdx.x;
  if (t >= E*4) return;
  int e = t >> 2, h = t & 3;
  int dst = ei[E + e];
  float ex = expf(d_logits[t] - d_segmax[dst*4+h]);
  d_exb[t] = ex;
  atomicAdd(d_denom + dst*4 + h, ex);
}

__global__ void k_agg(const int* __restrict__ ei, int E){
  int t = blockIdx.x*blockDim.x+threadIdx.x;
  if (t >= E*80) return;
  int e = t/80, r = t - e*80;
  int dst = ei[E + e];
  if (r < 32){
    int h = r >> 3;
    float alpha = d_exb[e*4+h]/(d_denom[dst*4+h] + 1e-12f);
    atomicAdd(d_agg0 + dst*32 + r, alpha*d_v0e[(size_t)e*32 + r]);
  } else {
    int r2 = r - 32, h = r2/12;
    float alpha = d_exb[e*4+h]/(d_denom[dst*4+h] + 1e-12f);
    atomicAdd(d_agg1 + dst*48 + r2, alpha*d_v1e[(size_t)e*48 + r2]);
  }
}

__global__ void k_node(const float* __restrict__ nf,
    const float* __restrict__ Wo0, const float* __restrict__ Wo1,
    const float* __restrict__ Wf10, const float* __restrict__ Wf11,
    const float* __restrict__ Wf20, const float* __restrict__ Wf21,
    float* __restrict__ out, int N)
{
  __shared__ float sx0[32], sx1[48], sa0[64], sa1[48];
  int n = blockIdx.x, t = threadIdx.x;
  if (t < 32){
    float acc = 0.f;
#pragma unroll
    for (int u = 0; u < 32; u++) acc += d_agg0[n*32+u]*Wo0[u*32+t];
    sx0[t] = nf[(size_t)n*80 + t] + acc*RS32f;
  } else if (t < 80){
    int r = t-32, w = r/3, i = r - w*3;
    float acc = 0.f;
#pragma unroll
    for (int u = 0; u < 16; u++) acc += d_agg1[n*48+u*3+i]*Wo1[u*16+w];
    sx1[r] = nf[(size_t)n*80 + 32 + r] + acc*0.25f;
  }
  __syncthreads();
  if (t < 64){
    float acc = 0.f;
#pragma unroll
    for (int u = 0; u < 32; u++) acc += sx0[u]*Wf10[u*64+t];
    float a = acc*RS32f;
    sa0[t] = a/(1.f+expf(-a));
  } else if (t < 112){
    int r = t-64, w = r/3, i = r - w*3;
    float acc = 0.f;
#pragma unroll
    for (int u = 0; u < 16; u++) acc += sx1[u*3+i]*Wf11[u*16+w];
    sa1[r] = acc*0.25f;
  }
  __syncthreads();
  if (t < 16){
    float x = sa1[t*3], y = sa1[t*3+1], z = sa1[t*3+2];
    float nm = sqrtf(x*x+y*y+z*z);
    float g = (nm < 1e-8f) ? 0.f : (nm/(1.f+expf(-nm)))/nm;
    sa1[t*3] = x*g; sa1[t*3+1] = y*g; sa1[t*3+2] = z*g;
  }
  __syncthreads();
  if (t < 32){
    float acc = 0.f;
#pragma unroll
    for (int u = 0; u < 64; u++) acc += sa0[u]*Wf20[u*32+t];
    out[(size_t)n*80 + t] = sx0[t] + acc*0.125f;
  } else if (t < 80){
    int r = t-32, w = r/3, i = r - w*3;
    float acc = 0.f;
#pragma unroll
    for (int u = 0; u < 16; u++) acc += sa1[u*3+i]*Wf21[u*16+w];
    out[(size_t)n*80 + t] = sx1[r] + acc*0.25f;
  }
}

extern "C" void kernel_launch(void* const* d_in, const int* in_sizes, int n_in,
                              void* d_out, int out_size){
  const float* nf   = (const float*)d_in[0];
  const int*   ei   = (const int*)  d_in[1];
  const float* esh  = (const float*)d_in[2];
  const float* emb  = (const float*)d_in[3];
  const float* Wq0  = (const float*)d_in[4];
  const float* Wq1  = (const float*)d_in[5];
  const float* Wk1  = (const float*)d_in[6];
  const float* bk1  = (const float*)d_in[7];
  const float* Wk2  = (const float*)d_in[8];
  const float* bk2  = (const float*)d_in[9];
  const float* Wv1  = (const float*)d_in[10];
  const float* bv1  = (const float*)d_in[11];
  const float* Wv2  = (const float*)d_in[12];
  const float* bv2  = (const float*)d_in[13];
  const float* Wd0  = (const float*)d_in[14];
  const float* Wd1  = (const float*)d_in[15];
  const float* Wo0  = (const float*)d_in[16];
  const float* Wo1  = (const float*)d_in[17];
  const float* Wf10 = (const float*)d_in[18];
  const float* Wf11 = (const float*)d_in[19];
  const float* Wf20 = (const float*)d_in[20];
  const float* Wf21 = (const float*)d_in[21];
  float* out = (float*)d_out;

  int N = in_sizes[0]/80;
  int E = in_sizes[1]/2;

  static int smCount = 0;
  if (!smCount){
    cudaFuncSetAttribute(k_edge, cudaFuncAttributeMaxDynamicSharedMemorySize, SMEM_BYTES);
    cudaDeviceGetAttribute(&smCount, cudaDevAttrMultiProcessorCount, 0);
    if (smCount <= 0) smCount = 148;
  }
  int nT = (E + 31)/32;
  int grid = nT < 3*smCount ? nT : 3*smCount;

  k_prep<<<(2*32*2304+255)/256, 256>>>(Wk2, Wv2);
  k_init<<<(N*48+255)/256, 256>>>(N);
  k_q<<<(N*80+255)/256, 256>>>(nf, Wq0, Wq1, N);
  k_edge<<<grid, 256, SMEM_BYTES>>>(nf, ei, esh, emb,
      Wk1, bk1, bk2, Wv1, bv1, bv2, Wd0, Wd1, N, E);
  k_ex<<<(E*4+255)/256, 256>>>(ei, E);
  k_agg<<<(E*80+255)/256, 256>>>(ei, E);
  k_node<<<N, 128>>>(nf, Wo0, Wo1, Wf10, Wf11, Wf20, Wf21, out, N);
}

// round 12
// speedup vs baseline: 1.4601x; 1.0397x over previous
#include <cuda_runtime.h>
#include <cuda_bf16.h>
#include <math.h>
#include <stdint.h>

#define MAX_N 2048
#define MAX_E 32768
#define RFANf   0.14433756729740643f  // 1/sqrt(48)
#define RSQRT3f 0.57735026918962576f
#define RS32f   0.17677669529663687f  // 1/sqrt(32)

__device__ float d_q0g[MAX_N*32];
__device__ float d_q1g[MAX_N*48];
__device__ float d_v0e[(size_t)MAX_E*32];
__device__ float d_v1e[(size_t)MAX_E*48];
__device__ float d_logits[MAX_E*4];
__device__ float d_exb[MAX_E*4];
__device__ float d_segmax[MAX_N*4];
__device__ float d_denom[MAX_N*4];
__device__ float d_agg0[MAX_N*32];
__device__ float d_agg1[MAX_N*48];
// W2 bf16 hi/lo, k-pair interleaved: row = set*64 + (lo?32:0) + kp, 2304 words/row
__device__ unsigned int d_W2p[128*2304];

__device__ __forceinline__ void atomicMaxF(float* a, float v){
  if (v >= 0.f) atomicMax((int*)a, __float_as_int(v));
  else atomicMin((unsigned int*)a, __float_as_uint(v));
}
__device__ __forceinline__ unsigned packbf(float x, float y){
  unsigned short ux = __bfloat16_as_ushort(__float2bfloat16(x));
  unsigned short uy = __bfloat16_as_ushort(__float2bfloat16(y));
  return ((unsigned)uy << 16) | (unsigned)ux;
}

__global__ void k_prep(const float* __restrict__ W2k, const float* __restrict__ W2v){
  int t = blockIdx.x*blockDim.x + threadIdx.x;
  if (t >= 2*32*2304) return;
  int s  = t / (32*2304);
  int r  = t - s*32*2304;
  int kp = r / 2304;
  int j  = r - kp*2304;
  const float* W = s ? W2v : W2k;
  float a0 = W[(2*kp)*2304 + j];
  float a1 = W[(2*kp+1)*2304 + j];
  __nv_bfloat16 h0 = __float2bfloat16(a0);
  __nv_bfloat16 h1 = __float2bfloat16(a1);
  d_W2p[(size_t)(s*64 + kp)*2304 + j]      = ((unsigned)__bfloat16_as_ushort(h1)<<16) | __bfloat16_as_ushort(h0);
  d_W2p[(size_t)(s*64 + 32 + kp)*2304 + j] = packbf(a0 - __bfloat162float(h0), a1 - __bfloat162float(h1));
}

__global__ void k_init(int N){
  int t = blockIdx.x*blockDim.x+threadIdx.x;
  if (t < N*4){ d_segmax[t] = -10.0f; d_denom[t] = 0.0f; }
  if (t < N*32) d_agg0[t] = 0.0f;
  if (t < N*48) d_agg1[t] = 0.0f;
}

__global__ void k_q(const float* __restrict__ nf, const float* __restrict__ Wq0,
                    const float* __restrict__ Wq1, int N){
  int t = blockIdx.x*blockDim.x+threadIdx.x;
  if (t >= N*80) return;
  int n = t/80, r = t - n*80;
  if (r < 32){
    int h = r>>3, w = r&7;
    const float* s = nf + (size_t)n*80;
    float acc = 0.f;
#pragma unroll
    for (int u = 0; u < 32; u++) acc += s[u]*Wq0[h*256+u*8+w];
    d_q0g[n*32+r] = acc*RS32f;
  } else {
    int rr = r-32, h = rr/12, q = rr - h*12, w = q/3, i = q - w*3;
    const float* v = nf + (size_t)n*80 + 32;
    float acc = 0.f;
#pragma unroll
    for (int u = 0; u < 16; u++) acc += v[u*3+i]*Wq1[h*64+u*4+w];
    d_q1g[n*48+rr] = acc*0.25f;
  }
}

// ---- smem layout (32-bit words), 32 edges/CTA, double-buffered B ----
#define OFF_B0   0        // 64*72
#define OFF_B1   4608     // 64*72 ; setup alias: W1(1088) + sA(2176) at +1088
#define BRS      72
#define OFF_WT   9216     // 32*72
#define WTP      72
#define ARS      68
#define OFF_O0   11520    // 32*36
#define O0P      36
#define OFF_S1   12672    // 32*20
#define S1P      20
#define OFF_V1   13312    // 32*52
#define V1P      52
#define OFF_SS   14976    // 32*36
#define SSP      36
#define OFF_VV   16128    // 32*52
#define VVP      52
#define OFF_CVV  17792    // 32*20
#define CVP      20
#define OFF_SH   18432    // 32*4
#define OFF_EMB  18560    // 32*16
#define OFF_IDX  19072    // 64
#define SMEM_WORDS 19136
#define SMEM_BYTES (SMEM_WORDS*4)   // 76544

__device__ __forceinline__ void cp16(void* dst, const void* src){
  uint32_t a = (uint32_t)__cvta_generic_to_shared(dst);
  asm volatile("cp.async.cg.shared.global [%0], [%1], 16;" :: "r"(a), "l"(src));
}
__device__ __forceinline__ void mma16(float* c, unsigned a0, unsigned a1, unsigned a2, unsigned a3,
                                      unsigned b0, unsigned b1){
  asm volatile(
    "mma.sync.aligned.m16n8k16.row.col.f32.bf16.bf16.f32 "
    "{%0,%1,%2,%3},{%4,%5,%6,%7},{%8,%9},{%0,%1,%2,%3};"
    : "+f"(c[0]), "+f"(c[1]), "+f"(c[2]), "+f"(c[3])
    : "r"(a0), "r"(a1), "r"(a2), "r"(a3), "r"(b0), "r"(b1));
}

__global__ void __launch_bounds__(256,3) k_edge(
    const float* __restrict__ nf, const int* __restrict__ ei,
    const float* __restrict__ esh, const float* __restrict__ emb,
    const float* __restrict__ W1k, const float* __restrict__ b1k,
    const float* __restrict__ b2k,
    const float* __restrict__ W1v, const float* __restrict__ b1v,
    const float* __restrict__ b2v,
    const float* __restrict__ Wd0, const float* __restrict__ Wd1,
    int N, int E)
{
  extern __shared__ float sm[];
  unsigned* sB  = (unsigned*)(sm + OFF_B0);       // two 4608-word buffers
  float* sW1  = sm + OFF_B1;                      // setup alias in buf1
  unsigned* sA  = (unsigned*)(sm + OFF_B1) + 1088;// setup alias in buf1
  float* sWT  = sm + OFF_WT;
  float* sO0  = sm + OFF_O0;
  float* sS1  = sm + OFF_S1;
  float* sV1  = sm + OFF_V1;
  float* sSS  = sm + OFF_SS;
  float* sVV  = sm + OFF_VV;
  float* sCVV = sm + OFF_CVV;
  float* sSH  = sm + OFF_SH;
  float* sEmb = sm + OFF_EMB;
  int*   sIdx = (int*)(sm + OFF_IDX);

  const int t    = threadIdx.x;
  const int lane = t & 31;
  const int wid  = t >> 5;
  const int wm   = wid >> 2, wn = wid & 3;   // warp: m16 (wm) x n16 (wn)
  const int g    = lane >> 2, c = lane & 3;
  const int rowA = (wm << 4) + g;
  const int nT   = (E + 31) >> 5;

  for (int et = blockIdx.x; et < nT; et += gridDim.x){
    const int eg0 = et << 5;
    __syncthreads();

    // prefetch B(set0, it0) into buf0 — slack = entire group setup
    {
      int r = t >> 2, part = t & 3;
      const unsigned* gsrc = d_W2p + (size_t)r*2304;
#pragma unroll
      for (int q = 0; q < 4; q++){
        int jw = (part << 2) + (q << 4);
        cp16(sB + r*BRS + jw, gsrc + jw);
      }
      asm volatile("cp.async.commit_group;");
    }

    if (t < 64){
      int e = t & 31, which = t >> 5;
      int eg = eg0 + e;
      sIdx[t] = (eg < E) ? ei[(size_t)which*E + eg] : 0;
    }
    if (t < 128){
      int e = t >> 2, cc = t & 3;
      int eg = eg0 + e;
      bool val = eg < E;
      sSH[e*4+cc] = val ? esh[(size_t)eg*4+cc] : 0.f;
      float4 z = make_float4(0,0,0,0);
      float4 d = val ? *(const float4*)(emb + (size_t)eg*16 + cc*4) : z;
      *(float4*)(sEmb + e*16 + cc*4) = d;
    }
    __syncthreads();

    // gather src node features (20 float4 per edge), padded strides
#pragma unroll
    for (int ph = 0; ph < 2; ph++){
      int p = t + ph*256;
      int e = p >> 4, f4 = p & 15;
      const float4* row = (const float4*)(nf + (size_t)sIdx[e]*80);
      float4 d = row[f4];
      if (f4 < 8) *((float4*)(sSS + e*SSP) + f4) = d;
      else        *((float4*)(sVV + e*VVP) + (f4-8)) = d;
    }
    if (t < 128){
      int e = t >> 2, f4 = 16 + (t & 3);
      const float4* row = (const float4*)(nf + (size_t)sIdx[e]*80);
      *((float4*)(sVV + e*VVP) + (f4-8)) = row[f4];
    }
    __syncthreads();

    // cvv
#pragma unroll
    for (int ph = 0; ph < 2; ph++){
      int p = t + ph*256;
      int e = p >> 4, u = p & 15;
      const float* vv = sVV + e*VVP + u*3;
      sCVV[e*CVP + u] = (vv[0]*sSH[e*4+1] + vv[1]*sSH[e*4+2] + vv[2]*sSH[e*4+3]) * RSQRT3f;
    }
    __syncthreads();

    // ---- two sets, sequential ----
#pragma unroll 1
    for (int s = 0; s < 2; s++){
      if (s == 1){
        // logits from k-set accumulators (before re-zero)
        __syncthreads();
        if (t < 128){
          int e = t >> 2, h = t & 3;
          int eg = eg0 + e;
          int dst = sIdx[32 + e];
          float k0r[8];
#pragma unroll
          for (int w = 0; w < 8; w++) k0r[w] = sO0[e*O0P + h*8 + w]*RFANf;
          const float* q0 = d_q0g + dst*32 + h*8;
          float l0 = 0.f;
#pragma unroll
          for (int v = 0; v < 8; v++){
            float tv = 0.f;
#pragma unroll
            for (int u = 0; u < 8; u++) tv += q0[u]*Wd0[u*8+v];
            l0 += tv*k0r[v];
          }
          float k1r[12];
#pragma unroll
          for (int w1 = 0; w1 < 4; w1++)
#pragma unroll
            for (int i = 0; i < 3; i++)
              k1r[w1*3+i] = (sS1[e*S1P+h*4+w1]*sSH[e*4+1+i] + sV1[e*V1P+h*12+w1*3+i])*RFANf;
          const float* q1 = d_q1g + dst*48 + h*12;
          float l1 = 0.f;
#pragma unroll
          for (int u = 0; u < 4; u++)
#pragma unroll
            for (int v = 0; v < 4; v++){
              float d3 = q1[u*3]*k1r[v*3] + q1[u*3+1]*k1r[v*3+1] + q1[u*3+2]*k1r[v*3+2];
              l1 += Wd1[u*4 + v]*d3;
            }
          float lg = (l0 + l1*RSQRT3f)*0.025f;
          lg = fminf(fmaxf(lg, -10.f), 10.f);
          if (eg < E){
            d_logits[eg*4 + h] = lg;
            atomicMaxF(d_segmax + dst*4 + h, lg);
          }
        }
        __syncthreads();

        // prefetch B(set1, it0) into buf0 — slack = entire set-1 setup
        {
          int r = t >> 2, part = t & 3;
          const unsigned* gsrc = d_W2p + (size_t)(64 + r)*2304;
#pragma unroll
          for (int q = 0; q < 4; q++){
            int jw = (part << 2) + (q << 4);
            cp16(sB + r*BRS + jw, gsrc + jw);
          }
          asm volatile("cp.async.commit_group;");
        }
      }

      // stage W1/b1 into buf1 alias; zero accumulators
      {
        const float* W1s = s ? W1v : W1k;
        const float* b1s = s ? b1v : b1k;
        for (int i = t; i < 1024; i += 256) sW1[i] = W1s[i];
        if (t < 64) sW1[1024+t] = b1s[t];
        for (int i = t; i < 864; i += 256) *(float4*)(sO0 + i*4) = make_float4(0,0,0,0);
      }
      __syncthreads();

      // hE for this set -> sA (bf16 hi/lo pairs), in buf1 alias
      {
        int e = t >> 3, kq = (t & 7) << 3;
        float v[8];
#pragma unroll
        for (int kk = 0; kk < 8; kk++){
          int k = kq + kk;
          float a = sW1[1024 + k];
#pragma unroll
          for (int b = 0; b < 16; b++) a += sEmb[e*16+b]*sW1[b*64+k];
          v[kk] = a/(1.f+expf(-a));
        }
        unsigned* arow = sA + e*ARS + (kq>>1);
#pragma unroll
        for (int p = 0; p < 4; p++){
          float x = v[2*p], y = v[2*p+1];
          __nv_bfloat16 hx = __float2bfloat16(x), hy = __float2bfloat16(y);
          arow[p]      = ((unsigned)__bfloat16_as_ushort(hy)<<16) | __bfloat16_as_ushort(hx);
          arow[32 + p] = packbf(x - __bfloat162float(hx), y - __bfloat162float(hy));
        }
      }
      __syncthreads();

      // hoist A fragments into registers for the whole set
      unsigned ah[4][4], al[4][4];
      {
        const unsigned* aP  = sA + rowA*ARS;
        const unsigned* aP8 = sA + (rowA+8)*ARS;
#pragma unroll
        for (int ks = 0; ks < 4; ks++){
          int kb = ks*8 + c;
          ah[ks][0] = aP[kb];    ah[ks][1] = aP8[kb];
          ah[ks][2] = aP[kb+4];  ah[ks][3] = aP8[kb+4];
          al[ks][0] = aP[32+kb]; al[ks][1] = aP8[32+kb];
          al[ks][2] = aP[32+kb+4]; al[ks][3] = aP8[32+kb+4];
        }
      }
      __syncthreads();   // sA/W1 dead; buf1 free for prefetch during tile 0

      // ---- 36 tiles of 64 j, double-buffered B ----
      int h = 0, off0 = 0;
      for (int it = 0; it < 36; it++){
        int j0 = it << 6;

        // B(it) delivered (issued one full tile earlier)
        asm volatile("cp.async.wait_group 0;");
        __syncthreads();   // B(it) visible; epilogue(it-1) done (sWT writable)

        // prefetch B(it+1) into the other buffer (full-tile slack)
        if (it + 1 < 36){
          int j02 = (it+1) << 6;
          unsigned* db = sB + ((it+1)&1)*4608;
          int r = t >> 2, part = t & 3;
          const unsigned* gsrc = d_W2p + (size_t)(s*64 + r)*2304 + j02;
#pragma unroll
          for (int q = 0; q < 4; q++){
            int jw = (part << 2) + (q << 4);
            cp16(db + r*BRS + jw, gsrc + jw);
          }
          asm volatile("cp.async.commit_group;");
        }

        const unsigned* sBb = sB + (it&1)*4608;

        // MMA m16 x n16 per warp, bias init
        float acc[2][4];
        {
          const float* b2p = s ? b2v : b2k;
#pragma unroll
          for (int nt = 0; nt < 2; nt++){
            float2 bb = *(const float2*)(b2p + j0 + (wn<<4) + (nt<<3) + 2*c);
            acc[nt][0] = bb.x; acc[nt][1] = bb.y; acc[nt][2] = bb.x; acc[nt][3] = bb.y;
          }
        }
#pragma unroll
        for (int ks = 0; ks < 4; ks++){
          int kb = ks*8 + c;
#pragma unroll
          for (int nt = 0; nt < 2; nt++){
            const unsigned* bP = sBb + kb*BRS + (wn<<4) + (nt<<3) + g;
            unsigned bh0 = bP[0],      bh1 = bP[4*BRS];
            unsigned bl0 = bP[32*BRS], bl1 = bP[36*BRS];
            mma16(acc[nt], ah[ks][0],ah[ks][1],ah[ks][2],ah[ks][3], bh0,bh1);
            mma16(acc[nt], al[ks][0],al[ks][1],al[ks][2],al[ks][3], bh0,bh1);
            mma16(acc[nt], ah[ks][0],ah[ks][1],ah[ks][2],ah[ks][3], bl0,bl1);
          }
        }
        // stage w tile
#pragma unroll
        for (int nt = 0; nt < 2; nt++){
          int jl = (wn<<4) + (nt<<3) + 2*c;
          *(float2*)(sWT + rowA*WTP + jl)     = make_float2(acc[nt][0], acc[nt][1]);
          *(float2*)(sWT + (rowA+8)*WTP + jl) = make_float2(acc[nt][2], acc[nt][3]);
        }
        __syncthreads();   // sWT staged; MMA(it) done by all (other buf safe next tile)

        // epilogue: contract this 64-j block (h/off0 loop-carried; padded strides)
        {
          if (off0 < 256){                     // ss -> out0 (coeff ss[u]*sh0)
            int u0 = off0 >> 3;
            int e = t >> 3, ow = t & 7;
            const float* wr = sWT + e*WTP + ow;
            float a = 0.f;
#pragma unroll
            for (int du = 0; du < 8; du++) a += sSS[e*SSP+u0+du]*wr[du*8];
            sO0[e*O0P + h*8 + ow] += a*sSH[e*4];
          } else if (off0 < 384){              // vv -> out0 (coeff cvv[u])
            int u0 = (off0-256) >> 3;
            int e = t >> 3, ow = t & 7;
            const float* wr = sWT + e*WTP + ow;
            float a = 0.f;
#pragma unroll
            for (int du = 0; du < 8; du++) a += sCVV[e*CVP+u0+du]*wr[du*8];
            sO0[e*O0P + h*8 + ow] += a;
          } else if (off0 < 512){              // sv -> s1 (coeff ss[u])
            if (t < 128){
              int u0 = (off0-384) >> 2;
              int e = t >> 2, w1 = t & 3;
              const float* wr = sWT + e*WTP + w1;
              float a = 0.f;
#pragma unroll
              for (int du = 0; du < 16; du++) a += sSS[e*SSP+u0+du]*wr[du*4];
              sS1[e*S1P + h*4 + w1] += a;
            }
          } else {                             // vs -> v1 (coeff vv[u,i]*sh0)
            for (int p = t; p < 384; p += 256){
              int e = p/12, r = p - e*12, w1 = r/3, i = r - w1*3;
              const float* wr = sWT + e*WTP + w1;
              float a = 0.f;
#pragma unroll
              for (int du = 0; du < 16; du++) a += sVV[e*VVP+du*3+i]*wr[du*4];
              sV1[e*V1P + h*12 + w1*3 + i] += a*sSH[e*4];
            }
          }
          off0 += 64;
          if (off0 == 576){ off0 = 0; h++; }
        }
        // epilogue->next-tile ordering handled by the top-of-tile sync
      }
      __syncthreads();   // all epilogues done before logits/outputs
    }

    // write v-set outputs (accumulators hold set 1 now)
#pragma unroll
    for (int ph = 0; ph < 4; ph++){
      int p = t + ph*256;
      int e = p >> 5, cc = p & 31;
      int eg = eg0 + e;
      if (eg < E) d_v0e[(size_t)eg*32 + cc] = sO0[e*O0P + cc]*RFANf;
    }
    for (int p = t; p < 1536; p += 256){
      int e = p/48, r = p - e*48;
      int h = r/12, q = r - h*12, w1 = q/3, i = q - w1*3;
      int eg = eg0 + e;
      if (eg < E)
        d_v1e[(size_t)eg*48 + r] =
          (sS1[e*S1P + h*4 + w1]*sSH[e*4+1+i] + sV1[e*V1P + r])*RFANf;
    }
  }
}

__global__ void k_ex(const int* __restrict__ ei, int E){
  int t = blockIdx.x*blockDim.x+threadIdx.x;
  if (t >= E*4) return;
  int e = t >> 2, h = t & 3;
  int dst = ei[E + e];
  float ex = expf(d_logits[t] - d_segmax[dst*4+h]);
  d_exb[t] = ex;
  atomicAdd(d_denom + dst*4 + h, ex);
}

__global__ void k_agg(const int* __restrict__ ei, int E){
  int t = blockIdx.x*blockDim.x+threadIdx.x;
  if (t >= E*80) return;
  int e = t/80, r = t - e*80;
  int dst = ei[E + e];
  if (r < 32){
    int h = r >> 3;
    float alpha = d_exb[e*4+h]/(d_denom[dst*4+h] + 1e-12f);
    atomicAdd(d_agg0 + dst*32 + r, alpha*d_v0e[(size_t)e*32 + r]);
  } else {
    int r2 = r - 32, h = r2/12;
    float alpha = d_exb[e*4+h]/(d_denom[dst*4+h] + 1e-12f);
    atomicAdd(d_agg1 + dst*48 + r2, alpha*d_v1e[(size_t)e*48 + r2]);
  }
}

__global__ void k_node(const float* __restrict__ nf,
    const float* __restrict__ Wo0, const float* __restrict__ Wo1,
    const float* __restrict__ Wf10, const float* __restrict__ Wf11,
    const float* __restrict__ Wf20, const float* __restrict__ Wf21,
    float* __restrict__ out, int N)
{
  __shared__ float sx0[32], sx1[48], sa0[64], sa1[48];
  int n = blockIdx.x, t = threadIdx.x;
  if (t < 32){
    float acc = 0.f;
#pragma unroll
    for (int u = 0; u < 32; u++) acc += d_agg0[n*32+u]*Wo0[u*32+t];
    sx0[t] = nf[(size_t)n*80 + t] + acc*RS32f;
  } else if (t < 80){
    int r = t-32, w = r/3, i = r - w*3;
    float acc = 0.f;
#pragma unroll
    for (int u = 0; u < 16; u++) acc += d_agg1[n*48+u*3+i]*Wo1[u*16+w];
    sx1[r] = nf[(size_t)n*80 + 32 + r] + acc*0.25f;
  }
  __syncthreads();
  if (t < 64){
    float acc = 0.f;
#pragma unroll
    for (int u = 0; u < 32; u++) acc += sx0[u]*Wf10[u*64+t];
    float a = acc*RS32f;
    sa0[t] = a/(1.f+expf(-a));
  } else if (t < 112){
    int r = t-64, w = r/3, i = r - w*3;
    float acc = 0.f;
#pragma unroll
    for (int u = 0; u < 16; u++) acc += sx1[u*3+i]*Wf11[u*16+w];
    sa1[r] = acc*0.25f;
  }
  __syncthreads();
  if (t < 16){
    float x = sa1[t*3], y = sa1[t*3+1], z = sa1[t*3+2];
    float nm = sqrtf(x*x+y*y+z*z);
    float g = (nm < 1e-8f) ? 0.f : (nm/(1.f+expf(-nm)))/nm;
    sa1[t*3] = x*g; sa1[t*3+1] = y*g; sa1[t*3+2] = z*g;
  }
  __syncthreads();
  if (t < 32){
    float acc = 0.f;
#pragma unroll
    for (int u = 0; u < 64; u++) acc += sa0[u]*Wf20[u*32+t];
    out[(size_t)n*80 + t] = sx0[t] + acc*0.125f;
  } else if (t < 80){
    int r = t-32, w = r/3, i = r - w*3;
    float acc = 0.f;
#pragma unroll
    for (int u = 0; u < 16; u++) acc += sa1[u*3+i]*Wf21[u*16+w];
    out[(size_t)n*80 + t] = sx1[r] + acc*0.25f;
  }
}

extern "C" void kernel_launch(void* const* d_in, const int* in_sizes, int n_in,
                              void* d_out, int out_size){
  const float* nf   = (const float*)d_in[0];
  const int*   ei   = (const int*)  d_in[1];
  const float* esh  = (const float*)d_in[2];
  const float* emb  = (const float*)d_in[3];
  const float* Wq0  = (const float*)d_in[4];
  const float* Wq1  = (const float*)d_in[5];
  const float* Wk1  = (const float*)d_in[6];
  const float* bk1  = (const float*)d_in[7];
  const float* Wk2  = (const float*)d_in[8];
  const float* bk2  = (const float*)d_in[9];
  const float* Wv1  = (const float*)d_in[10];
  const float* bv1  = (const float*)d_in[11];
  const float* Wv2  = (const float*)d_in[12];
  const float* bv2  = (const float*)d_in[13];
  const float* Wd0  = (const float*)d_in[14];
  const float* Wd1  = (const float*)d_in[15];
  const float* Wo0  = (const float*)d_in[16];
  const float* Wo1  = (const float*)d_in[17];
  const float* Wf10 = (const float*)d_in[18];
  const float* Wf11 = (const float*)d_in[19];
  const float* Wf20 = (const float*)d_in[20];
  const float* Wf21 = (const float*)d_in[21];
  float* out = (float*)d_out;

  int N = in_sizes[0]/80;
  int E = in_sizes[1]/2;

  static int smCount = 0;
  if (!smCount){
    cudaFuncSetAttribute(k_edge, cudaFuncAttributeMaxDynamicSharedMemorySize, SMEM_BYTES);
    cudaDeviceGetAttribute(&smCount, cudaDevAttrMultiProcessorCount, 0);
    if (smCount <= 0) smCount = 148;
  }
  int nT = (E + 31)/32;
  int grid = nT < 3*smCount ? nT : 3*smCount;

  k_prep<<<(2*32*2304+255)/256, 256>>>(Wk2, Wv2);
  k_init<<<(N*48+255)/256, 256>>>(N);
  k_q<<<(N*80+255)/256, 256>>>(nf, Wq0, Wq1, N);
  k_edge<<<grid, 256, SMEM_BYTES>>>(nf, ei, esh, emb,
      Wk1, bk1, bk2, Wv1, bv1, bv2, Wd0, Wd1, N, E);
  k_ex<<<(E*4+255)/256, 256>>>(ei, E);
  k_agg<<<(E*80+255)/256, 256>>>(ei, E);
  k_node<<<N, 128>>>(nf, Wo0, Wo1, Wf10, Wf11, Wf20, Wf21, out, N);
}

// round 13
// speedup vs baseline: 1.5705x; 1.0756x over previous
#include <cuda_runtime.h>
#include <cuda_bf16.h>
#include <math.h>
#include <stdint.h>

#define MAX_N 2048
#define MAX_E 32768
#define RFANf   0.14433756729740643f  // 1/sqrt(48)
#define RSQRT3f 0.57735026918962576f
#define RS32f   0.17677669529663687f  // 1/sqrt(32)

__device__ float d_q0g[MAX_N*32];
__device__ float d_q1g[MAX_N*48];
__device__ float d_v0e[(size_t)MAX_E*32];
__device__ float d_v1e[(size_t)MAX_E*48];
__device__ float d_logits[MAX_E*4];
__device__ float d_exb[MAX_E*4];
__device__ float d_segmax[MAX_N*4];
__device__ float d_denom[MAX_N*4];
__device__ float d_agg0[MAX_N*32];
__device__ float d_agg1[MAX_N*48];
// W2 bf16 hi/lo, k-pair interleaved: row = set*64 + (lo?32:0) + kp, 2304 words/row
__device__ unsigned int d_W2p[128*2304];

__device__ __forceinline__ void atomicMaxF(float* a, float v){
  if (v >= 0.f) atomicMax((int*)a, __float_as_int(v));
  else atomicMin((unsigned int*)a, __float_as_uint(v));
}
__device__ __forceinline__ unsigned packbf(float x, float y){
  unsigned short ux = __bfloat16_as_ushort(__float2bfloat16(x));
  unsigned short uy = __bfloat16_as_ushort(__float2bfloat16(y));
  return ((unsigned)uy << 16) | (unsigned)ux;
}

__global__ void k_prep(const float* __restrict__ W2k, const float* __restrict__ W2v){
  int t = blockIdx.x*blockDim.x + threadIdx.x;
  if (t >= 2*32*2304) return;
  int s  = t / (32*2304);
  int r  = t - s*32*2304;
  int kp = r / 2304;
  int j  = r - kp*2304;
  const float* W = s ? W2v : W2k;
  float a0 = W[(2*kp)*2304 + j];
  float a1 = W[(2*kp+1)*2304 + j];
  __nv_bfloat16 h0 = __float2bfloat16(a0);
  __nv_bfloat16 h1 = __float2bfloat16(a1);
  d_W2p[(size_t)(s*64 + kp)*2304 + j]      = ((unsigned)__bfloat16_as_ushort(h1)<<16) | __bfloat16_as_ushort(h0);
  d_W2p[(size_t)(s*64 + 32 + kp)*2304 + j] = packbf(a0 - __bfloat162float(h0), a1 - __bfloat162float(h1));
}

__global__ void k_init(int N){
  int t = blockIdx.x*blockDim.x+threadIdx.x;
  if (t < N*4){ d_segmax[t] = -10.0f; d_denom[t] = 0.0f; }
  if (t < N*32) d_agg0[t] = 0.0f;
  if (t < N*48) d_agg1[t] = 0.0f;
}

__global__ void k_q(const float* __restrict__ nf, const float* __restrict__ Wq0,
                    const float* __restrict__ Wq1, int N){
  int t = blockIdx.x*blockDim.x+threadIdx.x;
  if (t >= N*80) return;
  int n = t/80, r = t - n*80;
  if (r < 32){
    int h = r>>3, w = r&7;
    const float* s = nf + (size_t)n*80;
    float acc = 0.f;
#pragma unroll
    for (int u = 0; u < 32; u++) acc += s[u]*Wq0[h*256+u*8+w];
    d_q0g[n*32+r] = acc*RS32f;
  } else {
    int rr = r-32, h = rr/12, q = rr - h*12, w = q/3, i = q - w*3;
    const float* v = nf + (size_t)n*80 + 32;
    float acc = 0.f;
#pragma unroll
    for (int u = 0; u < 16; u++) acc += v[u*3+i]*Wq1[h*64+u*4+w];
    d_q1g[n*48+rr] = acc*0.25f;
  }
}

// ---- smem layout (32-bit words), 64 edges/CTA, 2 CTAs/SM ----
#define OFF_B0   0        // 64*72
#define OFF_B1   4608     // 64*72 ; setup alias: W1(1088)
#define BRS      72
#define OFF_WT   9216     // 64*72 ; setup alias: sA (64*68 = 4352)
#define WTP      72
#define ARS      68
#define OFF_O0   13824    // 64*40
#define O0P      40
#define OFF_S1   16384    // 64*20
#define S1P      20
#define OFF_V1   17664    // 64*48
#define V1P      48
#define OFF_SS   20736    // 64*36
#define SSP      36
#define OFF_VV   23040    // 64*48
#define VVP      48
#define OFF_CVV  26112    // 64*16
#define CVP      16
#define OFF_SH   27136    // 64*4
#define OFF_EMB  27392    // 64*16
#define OFF_IDX  28416    // 128
#define SMEM_WORDS 28544
#define SMEM_BYTES (SMEM_WORDS*4)   // 114176

__device__ __forceinline__ void cp16(void* dst, const void* src){
  uint32_t a = (uint32_t)__cvta_generic_to_shared(dst);
  asm volatile("cp.async.cg.shared.global [%0], [%1], 16;" :: "r"(a), "l"(src));
}
__device__ __forceinline__ void mma16(float* c, unsigned a0, unsigned a1, unsigned a2, unsigned a3,
                                      unsigned b0, unsigned b1){
  asm volatile(
    "mma.sync.aligned.m16n8k16.row.col.f32.bf16.bf16.f32 "
    "{%0,%1,%2,%3},{%4,%5,%6,%7},{%8,%9},{%0,%1,%2,%3};"
    : "+f"(c[0]), "+f"(c[1]), "+f"(c[2]), "+f"(c[3])
    : "r"(a0), "r"(a1), "r"(a2), "r"(a3), "r"(b0), "r"(b1));
}

__global__ void __launch_bounds__(256,2) k_edge(
    const float* __restrict__ nf, const int* __restrict__ ei,
    const float* __restrict__ esh, const float* __restrict__ emb,
    const float* __restrict__ W1k, const float* __restrict__ b1k,
    const float* __restrict__ b2k,
    const float* __restrict__ W1v, const float* __restrict__ b1v,
    const float* __restrict__ b2v,
    const float* __restrict__ Wd0, const float* __restrict__ Wd1,
    int N, int E)
{
  extern __shared__ float sm[];
  unsigned* sB  = (unsigned*)(sm + OFF_B0);       // two 4608-word buffers
  float* sW1  = sm + OFF_B1;                      // setup alias in buf1
  unsigned* sA  = (unsigned*)(sm + OFF_WT);       // setup alias in WT
  float* sWT  = sm + OFF_WT;
  float* sO0  = sm + OFF_O0;
  float* sS1  = sm + OFF_S1;
  float* sV1  = sm + OFF_V1;
  float* sSS  = sm + OFF_SS;
  float* sVV  = sm + OFF_VV;
  float* sCVV = sm + OFF_CVV;
  float* sSH  = sm + OFF_SH;
  float* sEmb = sm + OFF_EMB;
  int*   sIdx = (int*)(sm + OFF_IDX);

  const int t    = threadIdx.x;
  const int lane = t & 31;
  const int wid  = t >> 5;
  const int wm   = wid >> 2, wn = wid & 3;   // warp: m32 (wm) x n16 (wn)
  const int g    = lane >> 2, c = lane & 3;
  const int row0 = (wm << 5) + g;            // m-group 0 base row
  const int row1 = row0 + 16;                // m-group 1
  const int nT   = (E + 63) >> 6;

  for (int et = blockIdx.x; et < nT; et += gridDim.x){
    const int eg0 = et << 6;
    __syncthreads();

    // prefetch B(set0, it0) into buf0 — slack = entire group setup
    {
      int r = t >> 2, part = t & 3;
      const unsigned* gsrc = d_W2p + (size_t)r*2304;
#pragma unroll
      for (int q = 0; q < 4; q++){
        int jw = (part << 2) + (q << 4);
        cp16(sB + r*BRS + jw, gsrc + jw);
      }
      asm volatile("cp.async.commit_group;");
    }

    if (t < 128){
      int e = t & 63, which = t >> 6;
      int eg = eg0 + e;
      sIdx[t] = (eg < E) ? ei[(size_t)which*E + eg] : 0;
    }
    {
      int e = t >> 2, cc = t & 3;
      int eg = eg0 + e;
      bool val = eg < E;
      sSH[e*4+cc] = val ? esh[(size_t)eg*4+cc] : 0.f;
      float4 z = make_float4(0,0,0,0);
      float4 d = val ? *(const float4*)(emb + (size_t)eg*16 + cc*4) : z;
      *(float4*)(sEmb + e*16 + cc*4) = d;
    }
    __syncthreads();

    // gather src node features (20 float4 per edge), padded strides
#pragma unroll
    for (int ph = 0; ph < 4; ph++){
      int p = t + ph*256;
      int e = p >> 4, f4 = p & 15;
      const float4* row = (const float4*)(nf + (size_t)sIdx[e]*80);
      float4 d = row[f4];
      if (f4 < 8) *((float4*)(sSS + e*SSP) + f4) = d;
      else        *((float4*)(sVV + e*VVP) + (f4-8)) = d;
    }
    {
      int e = t >> 2, f4 = 16 + (t & 3);
      const float4* row = (const float4*)(nf + (size_t)sIdx[e]*80);
      *((float4*)(sVV + e*VVP) + (f4-8)) = row[f4];
    }
    __syncthreads();

    // cvv
#pragma unroll
    for (int ph = 0; ph < 4; ph++){
      int p = t + ph*256;
      int e = p >> 4, u = p & 15;
      const float* vv = sVV + e*VVP + u*3;
      sCVV[e*CVP + u] = (vv[0]*sSH[e*4+1] + vv[1]*sSH[e*4+2] + vv[2]*sSH[e*4+3]) * RSQRT3f;
    }
    __syncthreads();

    // ---- two sets, sequential ----
#pragma unroll 1
    for (int s = 0; s < 2; s++){
      if (s == 1){
        // logits from k-set accumulators (before re-zero)
        __syncthreads();
        {
          int e = t >> 2, h = t & 3;
          int eg = eg0 + e;
          int dst = sIdx[64 + e];
          float k0r[8];
#pragma unroll
          for (int w = 0; w < 8; w++) k0r[w] = sO0[e*O0P + h*8 + w]*RFANf;
          const float* q0 = d_q0g + dst*32 + h*8;
          float l0 = 0.f;
#pragma unroll
          for (int v = 0; v < 8; v++){
            float tv = 0.f;
#pragma unroll
            for (int u = 0; u < 8; u++) tv += q0[u]*Wd0[u*8+v];
            l0 += tv*k0r[v];
          }
          float k1r[12];
#pragma unroll
          for (int w1 = 0; w1 < 4; w1++)
#pragma unroll
            for (int i = 0; i < 3; i++)
              k1r[w1*3+i] = (sS1[e*S1P+h*4+w1]*sSH[e*4+1+i] + sV1[e*V1P+h*12+w1*3+i])*RFANf;
          const float* q1 = d_q1g + dst*48 + h*12;
          float l1 = 0.f;
#pragma unroll
          for (int u = 0; u < 4; u++)
#pragma unroll
            for (int v = 0; v < 4; v++){
              float d3 = q1[u*3]*k1r[v*3] + q1[u*3+1]*k1r[v*3+1] + q1[u*3+2]*k1r[v*3+2];
              l1 += Wd1[u*4 + v]*d3;
            }
          float lg = (l0 + l1*RSQRT3f)*0.025f;
          lg = fminf(fmaxf(lg, -10.f), 10.f);
          if (eg < E){
            d_logits[eg*4 + h] = lg;
            atomicMaxF(d_segmax + dst*4 + h, lg);
          }
        }
        __syncthreads();

        // prefetch B(set1, it0) into buf0 — slack = entire set-1 setup
        {
          int r = t >> 2, part = t & 3;
          const unsigned* gsrc = d_W2p + (size_t)(64 + r)*2304;
#pragma unroll
          for (int q = 0; q < 4; q++){
            int jw = (part << 2) + (q << 4);
            cp16(sB + r*BRS + jw, gsrc + jw);
          }
          asm volatile("cp.async.commit_group;");
        }
      }

      // stage W1/b1 into buf1 alias; zero accumulators (O0,S1,V1 contiguous 6912 w)
      {
        const float* W1s = s ? W1v : W1k;
        const float* b1s = s ? b1v : b1k;
        for (int i = t; i < 1024; i += 256) sW1[i] = W1s[i];
        if (t < 64) sW1[1024+t] = b1s[t];
        for (int i = t; i < 1728; i += 256) *(float4*)(sO0 + i*4) = make_float4(0,0,0,0);
      }
      __syncthreads();

      // hE for this set -> sA (bf16 hi/lo pairs), aliased in WT
      {
        int e = t >> 2, kq = (t & 3) << 4;
        float v[16];
#pragma unroll
        for (int kk = 0; kk < 16; kk++){
          int k = kq + kk;
          float a = sW1[1024 + k];
#pragma unroll
          for (int b = 0; b < 16; b++) a += sEmb[e*16+b]*sW1[b*64+k];
          v[kk] = a/(1.f+expf(-a));
        }
        unsigned* arow = sA + e*ARS + (kq>>1);
#pragma unroll
        for (int p = 0; p < 8; p++){
          float x = v[2*p], y = v[2*p+1];
          __nv_bfloat16 hx = __float2bfloat16(x), hy = __float2bfloat16(y);
          arow[p]      = ((unsigned)__bfloat16_as_ushort(hy)<<16) | __bfloat16_as_ushort(hx);
          arow[32 + p] = packbf(x - __bfloat162float(hx), y - __bfloat162float(hy));
        }
      }
      __syncthreads();

      // hoist A fragments (two m16 groups) into registers for the whole set
      unsigned ah0[4][4], al0[4][4], ah1[4][4], al1[4][4];
      {
        const unsigned* p0  = sA + row0*ARS;
        const unsigned* p08 = sA + (row0+8)*ARS;
        const unsigned* p1  = sA + row1*ARS;
        const unsigned* p18 = sA + (row1+8)*ARS;
#pragma unroll
        for (int ks = 0; ks < 4; ks++){
          int kb = ks*8 + c;
          ah0[ks][0] = p0[kb];     ah0[ks][1] = p08[kb];
          ah0[ks][2] = p0[kb+4];   ah0[ks][3] = p08[kb+4];
          al0[ks][0] = p0[32+kb];  al0[ks][1] = p08[32+kb];
          al0[ks][2] = p0[32+kb+4];al0[ks][3] = p08[32+kb+4];
          ah1[ks][0] = p1[kb];     ah1[ks][1] = p18[kb];
          ah1[ks][2] = p1[kb+4];   ah1[ks][3] = p18[kb+4];
          al1[ks][0] = p1[32+kb];  al1[ks][1] = p18[32+kb];
          al1[ks][2] = p1[32+kb+4];al1[ks][3] = p18[32+kb+4];
        }
      }
      __syncthreads();   // sA dead; sWT writable

      // ---- 36 tiles of 64 j, double-buffered B ----
      int h = 0, off0 = 0;
      for (int it = 0; it < 36; it++){
        int j0 = it << 6;

        asm volatile("cp.async.wait_group 0;");
        __syncthreads();   // B(it) visible; epilogue(it-1) done (sWT writable)

        // prefetch B(it+1) into the other buffer (full-tile slack)
        if (it + 1 < 36){
          int j02 = (it+1) << 6;
          unsigned* db = sB + ((it+1)&1)*4608;
          int r = t >> 2, part = t & 3;
          const unsigned* gsrc = d_W2p + (size_t)(s*64 + r)*2304 + j02;
#pragma unroll
          for (int q = 0; q < 4; q++){
            int jw = (part << 2) + (q << 4);
            cp16(db + r*BRS + jw, gsrc + jw);
          }
          asm volatile("cp.async.commit_group;");
        }

        const unsigned* sBb = sB + (it&1)*4608;

        // MMA: m32 x n16 per warp, B fragments shared across both m-groups
        float acc0[2][4], acc1[2][4];
        {
          const float* b2p = s ? b2v : b2k;
#pragma unroll
          for (int nt = 0; nt < 2; nt++){
            float2 bb = *(const float2*)(b2p + j0 + (wn<<4) + (nt<<3) + 2*c);
            acc0[nt][0] = bb.x; acc0[nt][1] = bb.y; acc0[nt][2] = bb.x; acc0[nt][3] = bb.y;
            acc1[nt][0] = bb.x; acc1[nt][1] = bb.y; acc1[nt][2] = bb.x; acc1[nt][3] = bb.y;
          }
        }
#pragma unroll
        for (int ks = 0; ks < 4; ks++){
          int kb = ks*8 + c;
#pragma unroll
          for (int nt = 0; nt < 2; nt++){
            const unsigned* bP = sBb + kb*BRS + (wn<<4) + (nt<<3) + g;
            unsigned bh0 = bP[0],      bh1 = bP[4*BRS];
            unsigned bl0 = bP[32*BRS], bl1 = bP[36*BRS];
            mma16(acc0[nt], ah0[ks][0],ah0[ks][1],ah0[ks][2],ah0[ks][3], bh0,bh1);
            mma16(acc0[nt], al0[ks][0],al0[ks][1],al0[ks][2],al0[ks][3], bh0,bh1);
            mma16(acc0[nt], ah0[ks][0],ah0[ks][1],ah0[ks][2],ah0[ks][3], bl0,bl1);
            mma16(acc1[nt], ah1[ks][0],ah1[ks][1],ah1[ks][2],ah1[ks][3], bh0,bh1);
            mma16(acc1[nt], al1[ks][0],al1[ks][1],al1[ks][2],al1[ks][3], bh0,bh1);
            mma16(acc1[nt], ah1[ks][0],ah1[ks][1],ah1[ks][2],ah1[ks][3], bl0,bl1);
          }
        }
        // stage w tile
#pragma unroll
        for (int nt = 0; nt < 2; nt++){
          int jl = (wn<<4) + (nt<<3) + 2*c;
          *(float2*)(sWT + row0*WTP + jl)      = make_float2(acc0[nt][0], acc0[nt][1]);
          *(float2*)(sWT + (row0+8)*WTP + jl)  = make_float2(acc0[nt][2], acc0[nt][3]);
          *(float2*)(sWT + row1*WTP + jl)      = make_float2(acc1[nt][0], acc1[nt][1]);
          *(float2*)(sWT + (row1+8)*WTP + jl)  = make_float2(acc1[nt][2], acc1[nt][3]);
        }
        __syncthreads();   // sWT staged; B(it) consumed

        // epilogue: contract this 64-j block (h/off0 loop-carried)
        {
          if (off0 < 256){                     // ss -> out0 (coeff ss[u]*sh0)
            int u0 = off0 >> 3;
#pragma unroll
            for (int ph = 0; ph < 2; ph++){
              int p = t + ph*256;
              int e = p >> 3, ow = p & 7;
              const float* wr = sWT + e*WTP + ow;
              float a = 0.f;
#pragma unroll
              for (int du = 0; du < 8; du++) a += sSS[e*SSP+u0+du]*wr[du*8];
              sO0[e*O0P + h*8 + ow] += a*sSH[e*4];
            }
          } else if (off0 < 384){              // vv -> out0 (coeff cvv[u])
            int u0 = (off0-256) >> 3;
#pragma unroll
            for (int ph = 0; ph < 2; ph++){
              int p = t + ph*256;
              int e = p >> 3, ow = p & 7;
              const float* wr = sWT + e*WTP + ow;
              float a = 0.f;
#pragma unroll
              for (int du = 0; du < 8; du++) a += sCVV[e*CVP+u0+du]*wr[du*8];
              sO0[e*O0P + h*8 + ow] += a;
            }
          } else if (off0 < 512){              // sv -> s1 (coeff ss[u])
            int u0 = (off0-384) >> 2;
            int e = t >> 2, w1 = t & 3;
            const float* wr = sWT + e*WTP + w1;
            float a = 0.f;
#pragma unroll
            for (int du = 0; du < 16; du++) a += sSS[e*SSP+u0+du]*wr[du*4];
            sS1[e*S1P + h*4 + w1] += a;
          } else {                             // vs -> v1 (coeff vv[u,i]*sh0)
            for (int p = t; p < 768; p += 256){
              int e = p/12, r = p - e*12, w1 = r/3, i = r - w1*3;
              const float* wr = sWT + e*WTP + w1;
              float a = 0.f;
#pragma unroll
              for (int du = 0; du < 16; du++) a += sVV[e*VVP+du*3+i]*wr[du*4];
              sV1[e*V1P + h*12 + w1*3 + i] += a*sSH[e*4];
            }
          }
          off0 += 64;
          if (off0 == 576){ off0 = 0; h++; }
        }
        // epilogue->next-tile ordering handled by the top-of-tile sync
      }
      __syncthreads();   // all epilogues done before logits/outputs
    }

    // write v-set outputs (accumulators hold set 1 now)
#pragma unroll
    for (int ph = 0; ph < 8; ph++){
      int p = t + ph*256;
      int e = p >> 5, cc = p & 31;
      int eg = eg0 + e;
      if (eg < E) d_v0e[(size_t)eg*32 + cc] = sO0[e*O0P + cc]*RFANf;
    }
    for (int p = t; p < 3072; p += 256){
      int e = p/48, r = p - e*48;
      int h = r/12, q = r - h*12, w1 = q/3, i = q - w1*3;
      int eg = eg0 + e;
      if (eg < E)
        d_v1e[(size_t)eg*48 + r] =
          (sS1[e*S1P + h*4 + w1]*sSH[e*4+1+i] + sV1[e*V1P + r])*RFANf;
    }
  }
}

__global__ void k_ex(const int* __restrict__ ei, int E){
  int t = blockIdx.x*blockDim.x+threadIdx.x;
  if (t >= E*4) return;
  int e = t >> 2, h = t & 3;
  int dst = ei[E + e];
  float ex = expf(d_logits[t] - d_segmax[dst*4+h]);
  d_exb[t] = ex;
  atomicAdd(d_denom + dst*4 + h, ex);
}

__global__ void k_agg(const int* __restrict__ ei, int E){
  int t = blockIdx.x*blockDim.x+threadIdx.x;
  if (t >= E*80) return;
  int e = t/80, r = t - e*80;
  int dst = ei[E + e];
  if (r < 32){
    int h = r >> 3;
    float alpha = d_exb[e*4+h]/(d_denom[dst*4+h] + 1e-12f);
    atomicAdd(d_agg0 + dst*32 + r, alpha*d_v0e[(size_t)e*32 + r]);
  } else {
    int r2 = r - 32, h = r2/12;
    float alpha = d_exb[e*4+h]/(d_denom[dst*4+h] + 1e-12f);
    atomicAdd(d_agg1 + dst*48 + r2, alpha*d_v1e[(size_t)e*48 + r2]);
  }
}

__global__ void k_node(const float* __restrict__ nf,
    const float* __restrict__ Wo0, const float* __restrict__ Wo1,
    const float* __restrict__ Wf10, const float* __restrict__ Wf11,
    const float* __restrict__ Wf20, const float* __restrict__ Wf21,
    float* __restrict__ out, int N)
{
  __shared__ float sx0[32], sx1[48], sa0[64], sa1[48];
  int n = blockIdx.x, t = threadIdx.x;
  if (t < 32){
    float acc = 0.f;
#pragma unroll
    for (int u = 0; u < 32; u++) acc += d_agg0[n*32+u]*Wo0[u*32+t];
    sx0[t] = nf[(size_t)n*80 + t] + acc*RS32f;
  } else if (t < 80){
    int r = t-32, w = r/3, i = r - w*3;
    float acc = 0.f;
#pragma unroll
    for (int u = 0; u < 16; u++) acc += d_agg1[n*48+u*3+i]*Wo1[u*16+w];
    sx1[r] = nf[(size_t)n*80 + 32 + r] + acc*0.25f;
  }
  __syncthreads();
  if (t < 64){
    float acc = 0.f;
#pragma unroll
    for (int u = 0; u < 32; u++) acc += sx0[u]*Wf10[u*64+t];
    float a = acc*RS32f;
    sa0[t] = a/(1.f+expf(-a));
  } else if (t < 112){
    int r = t-64, w = r/3, i = r - w*3;
    float acc = 0.f;
#pragma unroll
    for (int u = 0; u < 16; u++) acc += sx1[u*3+i]*Wf11[u*16+w];
    sa1[r] = acc*0.25f;
  }
  __syncthreads();
  if (t < 16){
    float x = sa1[t*3], y = sa1[t*3+1], z = sa1[t*3+2];
    float nm = sqrtf(x*x+y*y+z*z);
    float g = (nm < 1e-8f) ? 0.f : (nm/(1.f+expf(-nm)))/nm;
    sa1[t*3] = x*g; sa1[t*3+1] = y*g; sa1[t*3+2] = z*g;
  }
  __syncthreads();
  if (t < 32){
    float acc = 0.f;
#pragma unroll
    for (int u = 0; u < 64; u++) acc += sa0[u]*Wf20[u*32+t];
    out[(size_t)n*80 + t] = sx0[t] + acc*0.125f;
  } else if (t < 80){
    int r = t-32, w = r/3, i = r - w*3;
    float acc = 0.f;
#pragma unroll
    for (int u = 0; u < 16; u++) acc += sa1[u*3+i]*Wf21[u*16+w];
    out[(size_t)n*80 + t] = sx1[r] + acc*0.25f;
  }
}

extern "C" void kernel_launch(void* const* d_in, const int* in_sizes, int n_in,
                              void* d_out, int out_size){
  const float* nf   = (const float*)d_in[0];
  const int*   ei   = (const int*)  d_in[1];
  const float* esh  = (const float*)d_in[2];
  const float* emb  = (const float*)d_in[3];
  const float* Wq0  = (const float*)d_in[4];
  const float* Wq1  = (const float*)d_in[5];
  const float* Wk1  = (const float*)d_in[6];
  const float* bk1  = (const float*)d_in[7];
  const float* Wk2  = (const float*)d_in[8];
  const float* bk2  = (const float*)d_in[9];
  const float* Wv1  = (const float*)d_in[10];
  const float* bv1  = (const float*)d_in[11];
  const float* Wv2  = (const float*)d_in[12];
  const float* bv2  = (const float*)d_in[13];
  const float* Wd0  = (const float*)d_in[14];
  const float* Wd1  = (const float*)d_in[15];
  const float* Wo0  = (const float*)d_in[16];
  const float* Wo1  = (const float*)d_in[17];
  const float* Wf10 = (const float*)d_in[18];
  const float* Wf11 = (const float*)d_in[19];
  const float* Wf20 = (const float*)d_in[20];
  const float* Wf21 = (const float*)d_in[21];
  float* out = (float*)d_out;

  int N = in_sizes[0]/80;
  int E = in_sizes[1]/2;

  static int smCount = 0;
  if (!smCount){
    cudaFuncSetAttribute(k_edge, cudaFuncAttributeMaxDynamicSharedMemorySize, SMEM_BYTES);
    cudaDeviceGetAttribute(&smCount, cudaDevAttrMultiProcessorCount, 0);
    if (smCount <= 0) smCount = 148;
  }
  int nT = (E + 63)/64;
  int grid = nT < 2*smCount ? nT : 2*smCount;

  k_prep<<<(2*32*2304+255)/256, 256>>>(Wk2, Wv2);
  k_init<<<(N*48+255)/256, 256>>>(N);
  k_q<<<(N*80+255)/256, 256>>>(nf, Wq0, Wq1, N);
  k_edge<<<grid, 256, SMEM_BYTES>>>(nf, ei, esh, emb,
      Wk1, bk1, bk2, Wv1, bv1, bv2, Wd0, Wd1, N, E);
  k_ex<<<(E*4+255)/256, 256>>>(ei, E);
  k_agg<<<(E*80+255)/256, 256>>>(ei, E);
  k_node<<<N, 128>>>(nf, Wo0, Wo1, Wf10, Wf11, Wf20, Wf21, out, N);
}

// round 14
// speedup vs baseline: 1.5944x; 1.0153x over previous
#include <cuda_runtime.h>
#include <cuda_bf16.h>
#include <math.h>
#include <stdint.h>

#define MAX_N 2048
#define MAX_E 32768
#define RFANf   0.14433756729740643f  // 1/sqrt(48)
#define RSQRT3f 0.57735026918962576f
#define RS32f   0.17677669529663687f  // 1/sqrt(32)

__device__ float d_q0g[MAX_N*32];
__device__ float d_q1g[MAX_N*48];
__device__ float d_v0e[(size_t)MAX_E*32];
__device__ float d_v1e[(size_t)MAX_E*48];
__device__ float d_logits[MAX_E*4];
__device__ float d_exb[MAX_E*4];
__device__ float d_segmax[MAX_N*4];
__device__ float d_denom[MAX_N*4];
__device__ float d_agg0[MAX_N*32];
__device__ float d_agg1[MAX_N*48];
// W2 bf16 hi/lo, k-pair interleaved: row = set*64 + (lo?32:0) + kp, 2304 words/row
__device__ unsigned int d_W2p[128*2304];

__device__ __forceinline__ void atomicMaxF(float* a, float v){
  if (v >= 0.f) atomicMax((int*)a, __float_as_int(v));
  else atomicMin((unsigned int*)a, __float_as_uint(v));
}
__device__ __forceinline__ unsigned packbf(float x, float y){
  unsigned short ux = __bfloat16_as_ushort(__float2bfloat16(x));
  unsigned short uy = __bfloat16_as_ushort(__float2bfloat16(y));
  return ((unsigned)uy << 16) | (unsigned)ux;
}

__global__ void k_prep(const float* __restrict__ W2k, const float* __restrict__ W2v){
  int t = blockIdx.x*blockDim.x + threadIdx.x;
  if (t >= 2*32*2304) return;
  int s  = t / (32*2304);
  int r  = t - s*32*2304;
  int kp = r / 2304;
  int j  = r - kp*2304;
  const float* W = s ? W2v : W2k;
  float a0 = W[(2*kp)*2304 + j];
  float a1 = W[(2*kp+1)*2304 + j];
  __nv_bfloat16 h0 = __float2bfloat16(a0);
  __nv_bfloat16 h1 = __float2bfloat16(a1);
  d_W2p[(size_t)(s*64 + kp)*2304 + j]      = ((unsigned)__bfloat16_as_ushort(h1)<<16) | __bfloat16_as_ushort(h0);
  d_W2p[(size_t)(s*64 + 32 + kp)*2304 + j] = packbf(a0 - __bfloat162float(h0), a1 - __bfloat162float(h1));
}

__global__ void k_init(int N){
  int t = blockIdx.x*blockDim.x+threadIdx.x;
  if (t < N*4){ d_segmax[t] = -10.0f; d_denom[t] = 0.0f; }
  if (t < N*32) d_agg0[t] = 0.0f;
  if (t < N*48) d_agg1[t] = 0.0f;
}

__global__ void k_q(const float* __restrict__ nf, const float* __restrict__ Wq0,
                    const float* __restrict__ Wq1, int N){
  int t = blockIdx.x*blockDim.x+threadIdx.x;
  if (t >= N*80) return;
  int n = t/80, r = t - n*80;
  if (r < 32){
    int h = r>>3, w = r&7;
    const float* s = nf + (size_t)n*80;
    float acc = 0.f;
#pragma unroll
    for (int u = 0; u < 32; u++) acc += s[u]*Wq0[h*256+u*8+w];
    d_q0g[n*32+r] = acc*RS32f;
  } else {
    int rr = r-32, h = rr/12, q = rr - h*12, w = q/3, i = q - w*3;
    const float* v = nf + (size_t)n*80 + 32;
    float acc = 0.f;
#pragma unroll
    for (int u = 0; u < 16; u++) acc += v[u*3+i]*Wq1[h*64+u*4+w];
    d_q1g[n*48+rr] = acc*0.25f;
  }
}

// ---- smem layout (32-bit words), 64 edges/CTA, 2 CTAs/SM ----
#define OFF_B0   0        // 64*72
#define OFF_B1   4608     // 64*72 ; setup alias: W1(1088)
#define BRS      72
#define OFF_WT   9216     // 64*72 ; setup alias: sA (64*68 = 4352)
#define WTP      72
#define ARS      68
#define OFF_O0   13824    // 64*40
#define O0P      40
#define OFF_S1   16384    // 64*20
#define S1P      20
#define OFF_V1   17664    // 64*48
#define V1P      48
#define OFF_SS   20736    // 64*36
#define SSP      36
#define OFF_VV   23040    // 64*48
#define VVP      48
#define OFF_CVV  26112    // 64*16
#define CVP      16
#define OFF_SH   27136    // 64*4
#define OFF_EMB  27392    // 64*16
#define OFF_IDX  28416    // 128
#define SMEM_WORDS 28544
#define SMEM_BYTES (SMEM_WORDS*4)   // 114176

__device__ __forceinline__ void cp16(void* dst, const void* src){
  uint32_t a = (uint32_t)__cvta_generic_to_shared(dst);
  asm volatile("cp.async.cg.shared.global [%0], [%1], 16;" :: "r"(a), "l"(src));
}
__device__ __forceinline__ void mma16(float* c, unsigned a0, unsigned a1, unsigned a2, unsigned a3,
                                      unsigned b0, unsigned b1){
  asm volatile(
    "mma.sync.aligned.m16n8k16.row.col.f32.bf16.bf16.f32 "
    "{%0,%1,%2,%3},{%4,%5,%6,%7},{%8,%9},{%0,%1,%2,%3};"
    : "+f"(c[0]), "+f"(c[1]), "+f"(c[2]), "+f"(c[3])
    : "r"(a0), "r"(a1), "r"(a2), "r"(a3), "r"(b0), "r"(b1));
}

__global__ void __launch_bounds__(256,2) k_edge(
    const float* __restrict__ nf, const int* __restrict__ ei,
    const float* __restrict__ esh, const float* __restrict__ emb,
    const float* __restrict__ W1k, const float* __restrict__ b1k,
    const float* __restrict__ b2k,
    const float* __restrict__ W1v, const float* __restrict__ b1v,
    const float* __restrict__ b2v,
    const float* __restrict__ Wd0, const float* __restrict__ Wd1,
    int N, int E)
{
  extern __shared__ float sm[];
  unsigned* sB  = (unsigned*)(sm + OFF_B0);       // two 4608-word buffers
  float* sW1  = sm + OFF_B1;                      // setup alias in buf1
  unsigned* sA  = (unsigned*)(sm + OFF_WT);       // setup alias in WT
  float* sWT  = sm + OFF_WT;
  float* sO0  = sm + OFF_O0;
  float* sS1  = sm + OFF_S1;
  float* sV1  = sm + OFF_V1;
  float* sSS  = sm + OFF_SS;
  float* sVV  = sm + OFF_VV;
  float* sCVV = sm + OFF_CVV;
  float* sSH  = sm + OFF_SH;
  float* sEmb = sm + OFF_EMB;
  int*   sIdx = (int*)(sm + OFF_IDX);

  const int t    = threadIdx.x;
  const int lane = t & 31;
  const int wid  = t >> 5;
  const int wm   = wid >> 2, wn = wid & 3;   // warp: m32 (wm) x n16 (wn)
  const int g    = lane >> 2, c = lane & 3;
  const int row0 = (wm << 5) + g;            // m-group 0 base row
  const int row1 = row0 + 16;                // m-group 1

  const int eg0 = blockIdx.x << 6;           // one 64-edge group per block

  // prefetch B(set0, it0) into buf0 — slack = entire group setup
  {
    int r = t >> 2, part = t & 3;
    const unsigned* gsrc = d_W2p + (size_t)r*2304;
#pragma unroll
    for (int q = 0; q < 4; q++){
      int jw = (part << 2) + (q << 4);
      cp16(sB + r*BRS + jw, gsrc + jw);
    }
    asm volatile("cp.async.commit_group;");
  }

  if (t < 128){
    int e = t & 63, which = t >> 6;
    int eg = eg0 + e;
    sIdx[t] = (eg < E) ? ei[(size_t)which*E + eg] : 0;
  }
  {
    int e = t >> 2, cc = t & 3;
    int eg = eg0 + e;
    bool val = eg < E;
    sSH[e*4+cc] = val ? esh[(size_t)eg*4+cc] : 0.f;
    float4 z = make_float4(0,0,0,0);
    float4 d = val ? *(const float4*)(emb + (size_t)eg*16 + cc*4) : z;
    *(float4*)(sEmb + e*16 + cc*4) = d;
  }
  __syncthreads();

  // gather src node features (20 float4 per edge), padded strides
#pragma unroll
  for (int ph = 0; ph < 4; ph++){
    int p = t + ph*256;
    int e = p >> 4, f4 = p & 15;
    const float4* row = (const float4*)(nf + (size_t)sIdx[e]*80);
    float4 d = row[f4];
    if (f4 < 8) *((float4*)(sSS + e*SSP) + f4) = d;
    else        *((float4*)(sVV + e*VVP) + (f4-8)) = d;
  }
  {
    int e = t >> 2, f4 = 16 + (t & 3);
    const float4* row = (const float4*)(nf + (size_t)sIdx[e]*80);
    *((float4*)(sVV + e*VVP) + (f4-8)) = row[f4];
  }
  __syncthreads();

  // cvv
#pragma unroll
  for (int ph = 0; ph < 4; ph++){
    int p = t + ph*256;
    int e = p >> 4, u = p & 15;
    const float* vv = sVV + e*VVP + u*3;
    sCVV[e*CVP + u] = (vv[0]*sSH[e*4+1] + vv[1]*sSH[e*4+2] + vv[2]*sSH[e*4+3]) * RSQRT3f;
  }
  __syncthreads();

  // ---- two sets, sequential ----
#pragma unroll 1
  for (int s = 0; s < 2; s++){
    if (s == 1){
      // logits from k-set accumulators (before re-zero)
      __syncthreads();
      {
        int e = t >> 2, h = t & 3;
        int eg = eg0 + e;
        int dst = sIdx[64 + e];
        float k0r[8];
#pragma unroll
        for (int w = 0; w < 8; w++) k0r[w] = sO0[e*O0P + h*8 + w]*RFANf;
        const float* q0 = d_q0g + dst*32 + h*8;
        float l0 = 0.f;
#pragma unroll
        for (int v = 0; v < 8; v++){
          float tv = 0.f;
#pragma unroll
          for (int u = 0; u < 8; u++) tv += q0[u]*Wd0[u*8+v];
          l0 += tv*k0r[v];
        }
        float k1r[12];
#pragma unroll
        for (int w1 = 0; w1 < 4; w1++)
#pragma unroll
          for (int i = 0; i < 3; i++)
            k1r[w1*3+i] = (sS1[e*S1P+h*4+w1]*sSH[e*4+1+i] + sV1[e*V1P+h*12+w1*3+i])*RFANf;
        const float* q1 = d_q1g + dst*48 + h*12;
        float l1 = 0.f;
#pragma unroll
        for (int u = 0; u < 4; u++)
#pragma unroll
          for (int v = 0; v < 4; v++){
            float d3 = q1[u*3]*k1r[v*3] + q1[u*3+1]*k1r[v*3+1] + q1[u*3+2]*k1r[v*3+2];
            l1 += Wd1[u*4 + v]*d3;
          }
        float lg = (l0 + l1*RSQRT3f)*0.025f;
        lg = fminf(fmaxf(lg, -10.f), 10.f);
        if (eg < E){
          d_logits[eg*4 + h] = lg;
          atomicMaxF(d_segmax + dst*4 + h, lg);
        }
      }
      __syncthreads();

      // prefetch B(set1, it0) into buf0 — slack = entire set-1 setup
      {
        int r = t >> 2, part = t & 3;
        const unsigned* gsrc = d_W2p + (size_t)(64 + r)*2304;
#pragma unroll
        for (int q = 0; q < 4; q++){
          int jw = (part << 2) + (q << 4);
          cp16(sB + r*BRS + jw, gsrc + jw);
        }
        asm volatile("cp.async.commit_group;");
      }
    }

    // stage W1/b1 into buf1 alias; zero accumulators (O0,S1,V1 contiguous 6912 w)
    {
      const float* W1s = s ? W1v : W1k;
      const float* b1s = s ? b1v : b1k;
      for (int i = t; i < 1024; i += 256) sW1[i] = W1s[i];
      if (t < 64) sW1[1024+t] = b1s[t];
      for (int i = t; i < 1728; i += 256) *(float4*)(sO0 + i*4) = make_float4(0,0,0,0);
    }
    __syncthreads();

    // hE for this set -> sA (bf16 hi/lo pairs), aliased in WT
    {
      int e = t >> 2, kq = (t & 3) << 4;
      float v[16];
#pragma unroll
      for (int kk = 0; kk < 16; kk++){
        int k = kq + kk;
        float a = sW1[1024 + k];
#pragma unroll
        for (int b = 0; b < 16; b++) a += sEmb[e*16+b]*sW1[b*64+k];
        v[kk] = a/(1.f+expf(-a));
      }
      unsigned* arow = sA + e*ARS + (kq>>1);
#pragma unroll
      for (int p = 0; p < 8; p++){
        float x = v[2*p], y = v[2*p+1];
        __nv_bfloat16 hx = __float2bfloat16(x), hy = __float2bfloat16(y);
        arow[p]      = ((unsigned)__bfloat16_as_ushort(hy)<<16) | __bfloat16_as_ushort(hx);
        arow[32 + p] = packbf(x - __bfloat162float(hx), y - __bfloat162float(hy));
      }
    }
    __syncthreads();

    // hoist A fragments (two m16 groups) into registers for the whole set
    unsigned ah0[4][4], al0[4][4], ah1[4][4], al1[4][4];
    {
      const unsigned* p0  = sA + row0*ARS;
      const unsigned* p08 = sA + (row0+8)*ARS;
      const unsigned* p1  = sA + row1*ARS;
      const unsigned* p18 = sA + (row1+8)*ARS;
#pragma unroll
      for (int ks = 0; ks < 4; ks++){
        int kb = ks*8 + c;
        ah0[ks][0] = p0[kb];     ah0[ks][1] = p08[kb];
        ah0[ks][2] = p0[kb+4];   ah0[ks][3] = p08[kb+4];
        al0[ks][0] = p0[32+kb];  al0[ks][1] = p08[32+kb];
        al0[ks][2] = p0[32+kb+4];al0[ks][3] = p08[32+kb+4];
        ah1[ks][0] = p1[kb];     ah1[ks][1] = p18[kb];
        ah1[ks][2] = p1[kb+4];   ah1[ks][3] = p18[kb+4];
        al1[ks][0] = p1[32+kb];  al1[ks][1] = p18[32+kb];
        al1[ks][2] = p1[32+kb+4];al1[ks][3] = p18[32+kb+4];
      }
    }
    __syncthreads();   // sA dead; sWT writable

    // ---- 36 tiles of 64 j, double-buffered B ----
    int h = 0, off0 = 0;
    for (int it = 0; it < 36; it++){
      int j0 = it << 6;

      asm volatile("cp.async.wait_group 0;");
      __syncthreads();   // B(it) visible; epilogue(it-1) done (sWT writable)

      // prefetch B(it+1) into the other buffer (full-tile slack)
      if (it + 1 < 36){
        int j02 = (it+1) << 6;
        unsigned* db = sB + ((it+1)&1)*4608;
        int r = t >> 2, part = t & 3;
        const unsigned* gsrc = d_W2p + (size_t)(s*64 + r)*2304 + j02;
#pragma unroll
        for (int q = 0; q < 4; q++){
          int jw = (part << 2) + (q << 4);
          cp16(db + r*BRS + jw, gsrc + jw);
        }
        asm volatile("cp.async.commit_group;");
      }

      const unsigned* sBb = sB + (it&1)*4608;

      // MMA: m32 x n16 per warp, B fragments shared across both m-groups
      float acc0[2][4], acc1[2][4];
      {
        const float* b2p = s ? b2v : b2k;
#pragma unroll
        for (int nt = 0; nt < 2; nt++){
          float2 bb = *(const float2*)(b2p + j0 + (wn<<4) + (nt<<3) + 2*c);
          acc0[nt][0] = bb.x; acc0[nt][1] = bb.y; acc0[nt][2] = bb.x; acc0[nt][3] = bb.y;
          acc1[nt][0] = bb.x; acc1[nt][1] = bb.y; acc1[nt][2] = bb.x; acc1[nt][3] = bb.y;
        }
      }
#pragma unroll
      for (int ks = 0; ks < 4; ks++){
        int kb = ks*8 + c;
#pragma unroll
        for (int nt = 0; nt < 2; nt++){
          const unsigned* bP = sBb + kb*BRS + (wn<<4) + (nt<<3) + g;
          unsigned bh0 = bP[0],      bh1 = bP[4*BRS];
          unsigned bl0 = bP[32*BRS], bl1 = bP[36*BRS];
          mma16(acc0[nt], ah0[ks][0],ah0[ks][1],ah0[ks][2],ah0[ks][3], bh0,bh1);
          mma16(acc0[nt], al0[ks][0],al0[ks][1],al0[ks][2],al0[ks][3], bh0,bh1);
          mma16(acc0[nt], ah0[ks][0],ah0[ks][1],ah0[ks][2],ah0[ks][3], bl0,bl1);
          mma16(acc1[nt], ah1[ks][0],ah1[ks][1],ah1[ks][2],ah1[ks][3], bh0,bh1);
          mma16(acc1[nt], al1[ks][0],al1[ks][1],al1[ks][2],al1[ks][3], bh0,bh1);
          mma16(acc1[nt], ah1[ks][0],ah1[ks][1],ah1[ks][2],ah1[ks][3], bl0,bl1);
        }
      }
      // stage w tile
#pragma unroll
      for (int nt = 0; nt < 2; nt++){
        int jl = (wn<<4) + (nt<<3) + 2*c;
        *(float2*)(sWT + row0*WTP + jl)      = make_float2(acc0[nt][0], acc0[nt][1]);
        *(float2*)(sWT + (row0+8)*WTP + jl)  = make_float2(acc0[nt][2], acc0[nt][3]);
        *(float2*)(sWT + row1*WTP + jl)      = make_float2(acc1[nt][0], acc1[nt][1]);
        *(float2*)(sWT + (row1+8)*WTP + jl)  = make_float2(acc1[nt][2], acc1[nt][3]);
      }
      __syncthreads();   // sWT staged; B(it) consumed

      // epilogue: contract this 64-j block (h/off0 loop-carried)
      {
        if (off0 < 256){                     // ss -> out0 (coeff ss[u]*sh0)
          int u0 = off0 >> 3;
#pragma unroll
          for (int ph = 0; ph < 2; ph++){
            int p = t + ph*256;
            int e = p >> 3, ow = p & 7;
            const float* wr = sWT + e*WTP + ow;
            float a = 0.f;
#pragma unroll
            for (int du = 0; du < 8; du++) a += sSS[e*SSP+u0+du]*wr[du*8];
            sO0[e*O0P + h*8 + ow] += a*sSH[e*4];
          }
        } else if (off0 < 384){              // vv -> out0 (coeff cvv[u])
          int u0 = (off0-256) >> 3;
#pragma unroll
          for (int ph = 0; ph < 2; ph++){
            int p = t + ph*256;
            int e = p >> 3, ow = p & 7;
            const float* wr = sWT + e*WTP + ow;
            float a = 0.f;
#pragma unroll
            for (int du = 0; du < 8; du++) a += sCVV[e*CVP+u0+du]*wr[du*8];
            sO0[e*O0P + h*8 + ow] += a;
          }
        } else if (off0 < 512){              // sv -> s1 (coeff ss[u])
          int u0 = (off0-384) >> 2;
          int e = t >> 2, w1 = t & 3;
          const float* wr = sWT + e*WTP + w1;
          float a = 0.f;
#pragma unroll
          for (int du = 0; du < 16; du++) a += sSS[e*SSP+u0+du]*wr[du*4];
          sS1[e*S1P + h*4 + w1] += a;
        } else {                             // vs -> v1 (coeff vv[u,i]*sh0)
          for (int p = t; p < 768; p += 256){
            int e = p/12, r = p - e*12, w1 = r/3, i = r - w1*3;
            const float* wr = sWT + e*WTP + w1;
            float a = 0.f;
#pragma unroll
            for (int du = 0; du < 16; du++) a += sVV[e*VVP+du*3+i]*wr[du*4];
            sV1[e*V1P + h*12 + w1*3 + i] += a*sSH[e*4];
          }
        }
        off0 += 64;
        if (off0 == 576){ off0 = 0; h++; }
      }
      // epilogue->next-tile ordering handled by the top-of-tile sync
    }
    __syncthreads();   // all epilogues done before logits/outputs
  }

  // write v-set outputs (accumulators hold set 1 now)
#pragma unroll
  for (int ph = 0; ph < 8; ph++){
    int p = t + ph*256;
    int e = p >> 5, cc = p & 31;
    int eg = eg0 + e;
    if (eg < E) d_v0e[(size_t)eg*32 + cc] = sO0[e*O0P + cc]*RFANf;
  }
  for (int p = t; p < 3072; p += 256){
    int e = p/48, r = p - e*48;
    int h = r/12, q = r - h*12, w1 = q/3, i = q - w1*3;
    int eg = eg0 + e;
    if (eg < E)
      d_v1e[(size_t)eg*48 + r] =
        (sS1[e*S1P + h*4 + w1]*sSH[e*4+1+i] + sV1[e*V1P + r])*RFANf;
  }
}

__global__ void k_ex(const int* __restrict__ ei, int E){
  int t = blockIdx.x*blockDim.x+threadIdx.x;
  if (t >= E*4) return;
  int e = t >> 2, h = t & 3;
  int dst = ei[E + e];
  float ex = expf(d_logits[t] - d_segmax[dst*4+h]);
  d_exb[t] = ex;
  atomicAdd(d_denom + dst*4 + h, ex);
}

__global__ void k_agg(const int* __restrict__ ei, int E){
  int t = blockIdx.x*blockDim.x+threadIdx.x;
  if (t >= E*80) return;
  int e = t/80, r = t - e*80;
  int dst = ei[E + e];
  if (r < 32){
    int h = r >> 3;
    float alpha = d_exb[e*4+h]/(d_denom[dst*4+h] + 1e-12f);
    atomicAdd(d_agg0 + dst*32 + r, alpha*d_v0e[(size_t)e*32 + r]);
  } else {
    int r2 = r - 32, h = r2/12;
    float alpha = d_exb[e*4+h]/(d_denom[dst*4+h] + 1e-12f);
    atomicAdd(d_agg1 + dst*48 + r2, alpha*d_v1e[(size_t)e*48 + r2]);
  }
}

__global__ void k_node(const float* __restrict__ nf,
    const float* __restrict__ Wo0, const float* __restrict__ Wo1,
    const float* __restrict__ Wf10, const float* __restrict__ Wf11,
    const float* __restrict__ Wf20, const float* __restrict__ Wf21,
    float* __restrict__ out, int N)
{
  __shared__ float sx0[32], sx1[48], sa0[64], sa1[48];
  int n = blockIdx.x, t = threadIdx.x;
  if (t < 32){
    float acc = 0.f;
#pragma unroll
    for (int u = 0; u < 32; u++) acc += d_agg0[n*32+u]*Wo0[u*32+t];
    sx0[t] = nf[(size_t)n*80 + t] + acc*RS32f;
  } else if (t < 80){
    int r = t-32, w = r/3, i = r - w*3;
    float acc = 0.f;
#pragma unroll
    for (int u = 0; u < 16; u++) acc += d_agg1[n*48+u*3+i]*Wo1[u*16+w];
    sx1[r] = nf[(size_t)n*80 + 32 + r] + acc*0.25f;
  }
  __syncthreads();
  if (t < 64){
    float acc = 0.f;
#pragma unroll
    for (int u = 0; u < 32; u++) acc += sx0[u]*Wf10[u*64+t];
    float a = acc*RS32f;
    sa0[t] = a/(1.f+expf(-a));
  } else if (t < 112){
    int r = t-64, w = r/3, i = r - w*3;
    float acc = 0.f;
#pragma unroll
    for (int u = 0; u < 16; u++) acc += sx1[u*3+i]*Wf11[u*16+w];
    sa1[r] = acc*0.25f;
  }
  __syncthreads();
  if (t < 16){
    float x = sa1[t*3], y = sa1[t*3+1], z = sa1[t*3+2];
    float nm = sqrtf(x*x+y*y+z*z);
    float g = (nm < 1e-8f) ? 0.f : (nm/(1.f+expf(-nm)))/nm;
    sa1[t*3] = x*g; sa1[t*3+1] = y*g; sa1[t*3+2] = z*g;
  }
  __syncthreads();
  if (t < 32){
    float acc = 0.f;
#pragma unroll
    for (int u = 0; u < 64; u++) acc += sa0[u]*Wf20[u*32+t];
    out[(size_t)n*80 + t] = sx0[t] + acc*0.125f;
  } else if (t < 80){
    int r = t-32, w = r/3, i = r - w*3;
    float acc = 0.f;
#pragma unroll
    for (int u = 0; u < 16; u++) acc += sa1[u*3+i]*Wf21[u*16+w];
    out[(size_t)n*80 + t] = sx1[r] + acc*0.25f;
  }
}

extern "C" void kernel_launch(void* const* d_in, const int* in_sizes, int n_in,
                              void* d_out, int out_size){
  const float* nf   = (const float*)d_in[0];
  const int*   ei   = (const int*)  d_in[1];
  const float* esh  = (const float*)d_in[2];
  const float* emb  = (const float*)d_in[3];
  const float* Wq0  = (const float*)d_in[4];
  const float* Wq1  = (const float*)d_in[5];
  const float* Wk1  = (const float*)d_in[6];
  const float* bk1  = (const float*)d_in[7];
  const float* Wk2  = (const float*)d_in[8];
  const float* bk2  = (const float*)d_in[9];
  const float* Wv1  = (const float*)d_in[10];
  const float* bv1  = (const float*)d_in[11];
  const float* Wv2  = (const float*)d_in[12];
  const float* bv2  = (const float*)d_in[13];
  const float* Wd0  = (const float*)d_in[14];
  const float* Wd1  = (const float*)d_in[15];
  const float* Wo0  = (const float*)d_in[16];
  const float* Wo1  = (const float*)d_in[17];
  const float* Wf10 = (const float*)d_in[18];
  const float* Wf11 = (const float*)d_in[19];
  const float* Wf20 = (const float*)d_in[20];
  const float* Wf21 = (const float*)d_in[21];
  float* out = (float*)d_out;

  int N = in_sizes[0]/80;
  int E = in_sizes[1]/2;

  static int inited = 0;
  if (!inited){
    cudaFuncSetAttribute(k_edge, cudaFuncAttributeMaxDynamicSharedMemorySize, SMEM_BYTES);
    inited = 1;
  }
  int nT = (E + 63)/64;

  k_prep<<<(2*32*2304+255)/256, 256>>>(Wk2, Wv2);
  k_init<<<(N*48+255)/256, 256>>>(N);
  k_q<<<(N*80+255)/256, 256>>>(nf, Wq0, Wq1, N);
  k_edge<<<nT, 256, SMEM_BYTES>>>(nf, ei, esh, emb,
      Wk1, bk1, bk2, Wv1, bv1, bv2, Wd0, Wd1, N, E);
  k_ex<<<(E*4+255)/256, 256>>>(ei, E);
  k_agg<<<(E*80+255)/256, 256>>>(ei, E);
  k_node<<<N, 128>>>(nf, Wo0, Wo1, Wf10, Wf11, Wf20, Wf21, out, N);
}

// round 15
// speedup vs baseline: 1.6412x; 1.0294x over previous
#include <cuda_runtime.h>
#include <cuda_bf16.h>
#include <math.h>
#include <stdint.h>

#define MAX_N 2048
#define MAX_E 32768
#define RFANf   0.14433756729740643f  // 1/sqrt(48)
#define RSQRT3f 0.57735026918962576f
#define RS32f   0.17677669529663687f  // 1/sqrt(32)

__device__ float d_q0g[MAX_N*32];
__device__ float d_q1g[MAX_N*48];
__device__ float d_v0e[(size_t)MAX_E*32];
__device__ float d_v1e[(size_t)MAX_E*48];
__device__ float d_logits[MAX_E*4];
__device__ float d_exb[MAX_E*4];
__device__ float d_segmax[MAX_N*4];
__device__ float d_denom[MAX_N*4];
__device__ float d_agg0[MAX_N*32];
__device__ float d_agg1[MAX_N*48];
// W2 bf16 hi/lo, k-pair-adjacent layout:
// row = set*32 + (lo?16:0) + (ks*4+c), 4608 words/row, word index = j*2 + w
// w=0 -> k-pair row ks*8+c, w=1 -> k-pair row ks*8+c+4
__device__ unsigned int d_W2p[128*2304];

__device__ __forceinline__ void atomicMaxF(float* a, float v){
  if (v >= 0.f) atomicMax((int*)a, __float_as_int(v));
  else atomicMin((unsigned int*)a, __float_as_uint(v));
}
__device__ __forceinline__ unsigned packbf(float x, float y){
  unsigned short ux = __bfloat16_as_ushort(__float2bfloat16(x));
  unsigned short uy = __bfloat16_as_ushort(__float2bfloat16(y));
  return ((unsigned)uy << 16) | (unsigned)ux;
}

__global__ void k_prep(const float* __restrict__ W2k, const float* __restrict__ W2v){
  int t = blockIdx.x*blockDim.x + threadIdx.x;
  if (t >= 2*32*2304) return;
  int s  = t / (32*2304);
  int r  = t - s*32*2304;
  int kp = r / 2304;            // original k-pair row 0..31
  int j  = r - kp*2304;
  const float* W = s ? W2v : W2k;
  float a0 = W[(2*kp)*2304 + j];
  float a1 = W[(2*kp+1)*2304 + j];
  __nv_bfloat16 h0 = __float2bfloat16(a0);
  __nv_bfloat16 h1 = __float2bfloat16(a1);
  unsigned hi = ((unsigned)__bfloat16_as_ushort(h1)<<16) | __bfloat16_as_ushort(h0);
  unsigned lo = packbf(a0 - __bfloat162float(h0), a1 - __bfloat162float(h1));
  // kp = ks*8 + c + 4*w
  int ks = kp >> 3, rem = kp & 7;
  int w = rem >> 2, c = rem & 3;
  int p = (ks<<2) + c;
  d_W2p[(size_t)(s*32 + p)*4608 + j*2 + w]      = hi;
  d_W2p[(size_t)(s*32 + 16 + p)*4608 + j*2 + w] = lo;
}

__global__ void k_init(int N){
  int t = blockIdx.x*blockDim.x+threadIdx.x;
  if (t < N*4){ d_segmax[t] = -10.0f; d_denom[t] = 0.0f; }
  if (t < N*32) d_agg0[t] = 0.0f;
  if (t < N*48) d_agg1[t] = 0.0f;
}

__global__ void k_q(const float* __restrict__ nf, const float* __restrict__ Wq0,
                    const float* __restrict__ Wq1, int N){
  int t = blockIdx.x*blockDim.x+threadIdx.x;
  if (t >= N*80) return;
  int n = t/80, r = t - n*80;
  if (r < 32){
    int h = r>>3, w = r&7;
    const float* s = nf + (size_t)n*80;
    float acc = 0.f;
#pragma unroll
    for (int u = 0; u < 32; u++) acc += s[u]*Wq0[h*256+u*8+w];
    d_q0g[n*32+r] = acc*RS32f;
  } else {
    int rr = r-32, h = rr/12, q = rr - h*12, w = q/3, i = q - w*3;
    const float* v = nf + (size_t)n*80 + 32;
    float acc = 0.f;
#pragma unroll
    for (int u = 0; u < 16; u++) acc += v[u*3+i]*Wq1[h*64+u*4+w];
    d_q1g[n*48+rr] = acc*0.25f;
  }
}

// ---- smem layout (32-bit words), 64 edges/CTA, 2 CTAs/SM ----
#define OFF_B0   0        // 32 rows * 144
#define OFF_B1   4608     // 32 rows * 144 ; setup alias: W1(1088)
#define BRS      144
#define OFF_WT   9216     // 64*72 ; setup alias: sA (64*68 = 4352)
#define WTP      72
#define ARS      68
#define OFF_O0   13824    // 64*40
#define O0P      40
#define OFF_S1   16384    // 64*20
#define S1P      20
#define OFF_V1   17664    // 64*48
#define V1P      48
#define OFF_SS   20736    // 64*36
#define SSP      36
#define OFF_VV   23040    // 64*48
#define VVP      48
#define OFF_CVV  26112    // 64*16
#define CVP      16
#define OFF_SH   27136    // 64*4
#define OFF_EMB  27392    // 64*16
#define OFF_IDX  28416    // 128
#define SMEM_WORDS 28544
#define SMEM_BYTES (SMEM_WORDS*4)   // 114176

__device__ __forceinline__ void cp16(void* dst, const void* src){
  uint32_t a = (uint32_t)__cvta_generic_to_shared(dst);
  asm volatile("cp.async.cg.shared.global [%0], [%1], 16;" :: "r"(a), "l"(src));
}
__device__ __forceinline__ void mma16(float* c, unsigned a0, unsigned a1, unsigned a2, unsigned a3,
                                      unsigned b0, unsigned b1){
  asm volatile(
    "mma.sync.aligned.m16n8k16.row.col.f32.bf16.bf16.f32 "
    "{%0,%1,%2,%3},{%4,%5,%6,%7},{%8,%9},{%0,%1,%2,%3};"
    : "+f"(c[0]), "+f"(c[1]), "+f"(c[2]), "+f"(c[3])
    : "r"(a0), "r"(a1), "r"(a2), "r"(a3), "r"(b0), "r"(b1));
}

__global__ void __launch_bounds__(256,2) k_edge(
    const float* __restrict__ nf, const int* __restrict__ ei,
    const float* __restrict__ esh, const float* __restrict__ emb,
    const float* __restrict__ W1k, const float* __restrict__ b1k,
    const float* __restrict__ b2k,
    const float* __restrict__ W1v, const float* __restrict__ b1v,
    const float* __restrict__ b2v,
    const float* __restrict__ Wd0, const float* __restrict__ Wd1,
    int N, int E)
{
  extern __shared__ float sm[];
  unsigned* sB  = (unsigned*)(sm + OFF_B0);       // two 4608-word buffers
  float* sW1  = sm + OFF_B1;                      // setup alias in buf1
  unsigned* sA  = (unsigned*)(sm + OFF_WT);       // setup alias in WT
  float* sWT  = sm + OFF_WT;
  float* sO0  = sm + OFF_O0;
  float* sS1  = sm + OFF_S1;
  float* sV1  = sm + OFF_V1;
  float* sSS  = sm + OFF_SS;
  float* sVV  = sm + OFF_VV;
  float* sCVV = sm + OFF_CVV;
  float* sSH  = sm + OFF_SH;
  float* sEmb = sm + OFF_EMB;
  int*   sIdx = (int*)(sm + OFF_IDX);

  const int t    = threadIdx.x;
  const int lane = t & 31;
  const int wid  = t >> 5;
  const int wm   = wid >> 2, wn = wid & 3;   // warp: m32 (wm) x n16 (wn)
  const int g    = lane >> 2, c = lane & 3;
  const int row0 = (wm << 5) + g;            // m-group 0 base row
  const int row1 = row0 + 16;                // m-group 1

  const int eg0 = blockIdx.x << 6;           // one 64-edge group per block

  // prefetch B(set0, it0) into buf0 — slack = entire group setup
  {
    int r = t >> 3, ch = t & 7;
    const unsigned* gsrc = d_W2p + (size_t)r*4608;
#pragma unroll
    for (int q = 0; q < 4; q++){
      int jw = (ch + (q<<3)) << 2;
      cp16(sB + r*BRS + jw, gsrc + jw);
    }
    asm volatile("cp.async.commit_group;");
  }

  if (t < 128){
    int e = t & 63, which = t >> 6;
    int eg = eg0 + e;
    sIdx[t] = (eg < E) ? ei[(size_t)which*E + eg] : 0;
  }
  {
    int e = t >> 2, cc = t & 3;
    int eg = eg0 + e;
    bool val = eg < E;
    sSH[e*4+cc] = val ? esh[(size_t)eg*4+cc] : 0.f;
    float4 z = make_float4(0,0,0,0);
    float4 d = val ? *(const float4*)(emb + (size_t)eg*16 + cc*4) : z;
    *(float4*)(sEmb + e*16 + cc*4) = d;
  }
  __syncthreads();

  // gather src node features (20 float4 per edge), padded strides
#pragma unroll
  for (int ph = 0; ph < 4; ph++){
    int p = t + ph*256;
    int e = p >> 4, f4 = p & 15;
    const float4* row = (const float4*)(nf + (size_t)sIdx[e]*80);
    float4 d = row[f4];
    if (f4 < 8) *((float4*)(sSS + e*SSP) + f4) = d;
    else        *((float4*)(sVV + e*VVP) + (f4-8)) = d;
  }
  {
    int e = t >> 2, f4 = 16 + (t & 3);
    const float4* row = (const float4*)(nf + (size_t)sIdx[e]*80);
    *((float4*)(sVV + e*VVP) + (f4-8)) = row[f4];
  }
  __syncthreads();

  // cvv
#pragma unroll
  for (int ph = 0; ph < 4; ph++){
    int p = t + ph*256;
    int e = p >> 4, u = p & 15;
    const float* vv = sVV + e*VVP + u*3;
    sCVV[e*CVP + u] = (vv[0]*sSH[e*4+1] + vv[1]*sSH[e*4+2] + vv[2]*sSH[e*4+3]) * RSQRT3f;
  }
  __syncthreads();

  // ---- two sets, sequential ----
#pragma unroll 1
  for (int s = 0; s < 2; s++){
    if (s == 1){
      // logits from k-set accumulators (before re-zero)
      __syncthreads();
      {
        int e = t >> 2, h = t & 3;
        int eg = eg0 + e;
        int dst = sIdx[64 + e];
        float k0r[8];
#pragma unroll
        for (int w = 0; w < 8; w++) k0r[w] = sO0[e*O0P + h*8 + w]*RFANf;
        const float* q0 = d_q0g + dst*32 + h*8;
        float l0 = 0.f;
#pragma unroll
        for (int v = 0; v < 8; v++){
          float tv = 0.f;
#pragma unroll
          for (int u = 0; u < 8; u++) tv += q0[u]*Wd0[u*8+v];
          l0 += tv*k0r[v];
        }
        float k1r[12];
#pragma unroll
        for (int w1 = 0; w1 < 4; w1++)
#pragma unroll
          for (int i = 0; i < 3; i++)
            k1r[w1*3+i] = (sS1[e*S1P+h*4+w1]*sSH[e*4+1+i] + sV1[e*V1P+h*12+w1*3+i])*RFANf;
        const float* q1 = d_q1g + dst*48 + h*12;
        float l1 = 0.f;
#pragma unroll
        for (int u = 0; u < 4; u++)
#pragma unroll
          for (int v = 0; v < 4; v++){
            float d3 = q1[u*3]*k1r[v*3] + q1[u*3+1]*k1r[v*3+1] + q1[u*3+2]*k1r[v*3+2];
            l1 += Wd1[u*4 + v]*d3;
          }
        float lg = (l0 + l1*RSQRT3f)*0.025f;
        lg = fminf(fmaxf(lg, -10.f), 10.f);
        if (eg < E){
          d_logits[eg*4 + h] = lg;
          atomicMaxF(d_segmax + dst*4 + h, lg);
        }
      }
      __syncthreads();

      // prefetch B(set1, it0) into buf0 — slack = entire set-1 setup
      {
        int r = t >> 3, ch = t & 7;
        const unsigned* gsrc = d_W2p + (size_t)(32 + r)*4608;
#pragma unroll
        for (int q = 0; q < 4; q++){
          int jw = (ch + (q<<3)) << 2;
          cp16(sB + r*BRS + jw, gsrc + jw);
        }
        asm volatile("cp.async.commit_group;");
      }
    }

    // stage W1/b1 into buf1 alias; zero accumulators (O0,S1,V1 contiguous 6912 w)
    {
      const float* W1s = s ? W1v : W1k;
      const float* b1s = s ? b1v : b1k;
      for (int i = t; i < 1024; i += 256) sW1[i] = W1s[i];
      if (t < 64) sW1[1024+t] = b1s[t];
      for (int i = t; i < 1728; i += 256) *(float4*)(sO0 + i*4) = make_float4(0,0,0,0);
    }
    __syncthreads();

    // hE for this set -> sA (bf16 hi/lo pairs), aliased in WT
    {
      int e = t >> 2, kq = (t & 3) << 4;
      float v[16];
#pragma unroll
      for (int kk = 0; kk < 16; kk++){
        int k = kq + kk;
        float a = sW1[1024 + k];
#pragma unroll
        for (int b = 0; b < 16; b++) a += sEmb[e*16+b]*sW1[b*64+k];
        v[kk] = a/(1.f+expf(-a));
      }
      unsigned* arow = sA + e*ARS + (kq>>1);
#pragma unroll
      for (int p = 0; p < 8; p++){
        float x = v[2*p], y = v[2*p+1];
        __nv_bfloat16 hx = __float2bfloat16(x), hy = __float2bfloat16(y);
        arow[p]      = ((unsigned)__bfloat16_as_ushort(hy)<<16) | __bfloat16_as_ushort(hx);
        arow[32 + p] = packbf(x - __bfloat162float(hx), y - __bfloat162float(hy));
      }
    }
    __syncthreads();

    // hoist A fragments (two m16 groups) into registers for the whole set
    unsigned ah0[4][4], al0[4][4], ah1[4][4], al1[4][4];
    {
      const unsigned* p0  = sA + row0*ARS;
      const unsigned* p08 = sA + (row0+8)*ARS;
      const unsigned* p1  = sA + row1*ARS;
      const unsigned* p18 = sA + (row1+8)*ARS;
#pragma unroll
      for (int ks = 0; ks < 4; ks++){
        int kb = ks*8 + c;
        ah0[ks][0] = p0[kb];     ah0[ks][1] = p08[kb];
        ah0[ks][2] = p0[kb+4];   ah0[ks][3] = p08[kb+4];
        al0[ks][0] = p0[32+kb];  al0[ks][1] = p08[32+kb];
        al0[ks][2] = p0[32+kb+4];al0[ks][3] = p08[32+kb+4];
        ah1[ks][0] = p1[kb];     ah1[ks][1] = p18[kb];
        ah1[ks][2] = p1[kb+4];   ah1[ks][3] = p18[kb+4];
        al1[ks][0] = p1[32+kb];  al1[ks][1] = p18[32+kb];
        al1[ks][2] = p1[32+kb+4];al1[ks][3] = p18[32+kb+4];
      }
    }
    __syncthreads();   // sA dead; sWT writable

    // ---- 36 tiles of 64 j, double-buffered B ----
    int h = 0, off0 = 0;
    for (int it = 0; it < 36; it++){
      int j0 = it << 6;

      asm volatile("cp.async.wait_group 0;");
      __syncthreads();   // B(it) visible; epilogue(it-1) done (sWT writable)

      // prefetch B(it+1) into the other buffer (full-tile slack)
      if (it + 1 < 36){
        int j02 = (it+1) << 6;
        unsigned* db = sB + ((it+1)&1)*4608;
        int r = t >> 3, ch = t & 7;
        const unsigned* gsrc = d_W2p + (size_t)(s*32 + r)*4608 + j02*2;
#pragma unroll
        for (int q = 0; q < 4; q++){
          int jw = (ch + (q<<3)) << 2;
          cp16(db + r*BRS + jw, gsrc + jw);
        }
        asm volatile("cp.async.commit_group;");
      }

      const unsigned* sBb = sB + (it&1)*4608;

      // MMA: m32 x n16 per warp, B fragments LDS.64 (k-pair adjacent)
      float acc0[2][4], acc1[2][4];
      {
        const float* b2p = s ? b2v : b2k;
#pragma unroll
        for (int nt = 0; nt < 2; nt++){
          float2 bb = *(const float2*)(b2p + j0 + (wn<<4) + (nt<<3) + 2*c);
          acc0[nt][0] = bb.x; acc0[nt][1] = bb.y; acc0[nt][2] = bb.x; acc0[nt][3] = bb.y;
          acc1[nt][0] = bb.x; acc1[nt][1] = bb.y; acc1[nt][2] = bb.x; acc1[nt][3] = bb.y;
        }
      }
#pragma unroll
      for (int ks = 0; ks < 4; ks++){
#pragma unroll
        for (int nt = 0; nt < 2; nt++){
          const unsigned long long* bQ = (const unsigned long long*)
            (sBb + ((ks<<2) + c)*BRS + (((wn<<4) + (nt<<3) + g)<<1));
          unsigned long long bh = bQ[0];
          unsigned long long bl = bQ[16*BRS/2];
          unsigned bh0 = (unsigned)bh, bh1 = (unsigned)(bh>>32);
          unsigned bl0 = (unsigned)bl, bl1 = (unsigned)(bl>>32);
          mma16(acc0[nt], ah0[ks][0],ah0[ks][1],ah0[ks][2],ah0[ks][3], bh0,bh1);
          mma16(acc0[nt], al0[ks][0],al0[ks][1],al0[ks][2],al0[ks][3], bh0,bh1);
          mma16(acc0[nt], ah0[ks][0],ah0[ks][1],ah0[ks][2],ah0[ks][3], bl0,bl1);
          mma16(acc1[nt], ah1[ks][0],ah1[ks][1],ah1[ks][2],ah1[ks][3], bh0,bh1);
          mma16(acc1[nt], al1[ks][0],al1[ks][1],al1[ks][2],al1[ks][3], bh0,bh1);
          mma16(acc1[nt], ah1[ks][0],ah1[ks][1],ah1[ks][2],ah1[ks][3], bl0,bl1);
        }
      }
      // stage w tile
#pragma unroll
      for (int nt = 0; nt < 2; nt++){
        int jl = (wn<<4) + (nt<<3) + 2*c;
        *(float2*)(sWT + row0*WTP + jl)      = make_float2(acc0[nt][0], acc0[nt][1]);
        *(float2*)(sWT + (row0+8)*WTP + jl)  = make_float2(acc0[nt][2], acc0[nt][3]);
        *(float2*)(sWT + row1*WTP + jl)      = make_float2(acc1[nt][0], acc1[nt][1]);
        *(float2*)(sWT + (row1+8)*WTP + jl)  = make_float2(acc1[nt][2], acc1[nt][3]);
      }
      __syncthreads();   // sWT staged; B(it) consumed

      // epilogue: contract this 64-j block (h/off0 loop-carried; vectorized coeffs)
      {
        if (off0 < 256){                     // ss -> out0 (coeff ss[u]*sh0)
          int u0 = off0 >> 3;
#pragma unroll
          for (int ph = 0; ph < 2; ph++){
            int p = t + ph*256;
            int e = p >> 3, ow = p & 7;
            const float* wr = sWT + e*WTP + ow;
            float4 s0 = *(const float4*)(sSS + e*SSP + u0);
            float4 s1 = *(const float4*)(sSS + e*SSP + u0 + 4);
            float a = s0.x*wr[0] + s0.y*wr[8] + s0.z*wr[16] + s0.w*wr[24]
                    + s1.x*wr[32] + s1.y*wr[40] + s1.z*wr[48] + s1.w*wr[56];
            sO0[e*O0P + h*8 + ow] += a*sSH[e*4];
          }
        } else if (off0 < 384){              // vv -> out0 (coeff cvv[u])
          int u0 = (off0-256) >> 3;
#pragma unroll
          for (int ph = 0; ph < 2; ph++){
            int p = t + ph*256;
            int e = p >> 3, ow = p & 7;
            const float* wr = sWT + e*WTP + ow;
            float4 s0 = *(const float4*)(sCVV + e*CVP + u0);
            float4 s1 = *(const float4*)(sCVV + e*CVP + u0 + 4);
            float a = s0.x*wr[0] + s0.y*wr[8] + s0.z*wr[16] + s0.w*wr[24]
                    + s1.x*wr[32] + s1.y*wr[40] + s1.z*wr[48] + s1.w*wr[56];
            sO0[e*O0P + h*8 + ow] += a;
          }
        } else if (off0 < 512){              // sv -> s1 (coeff ss[u])
          int u0 = (off0-384) >> 2;
          int e = t >> 2, w1 = t & 3;
          const float* wr = sWT + e*WTP + w1;
          float a = 0.f;
#pragma unroll
          for (int q4 = 0; q4 < 4; q4++){
            float4 sv = *(const float4*)(sSS + e*SSP + u0 + q4*4);
            a += sv.x*wr[q4*16] + sv.y*wr[q4*16+4] + sv.z*wr[q4*16+8] + sv.w*wr[q4*16+12];
          }
          sS1[e*S1P + h*4 + w1] += a;
        } else {                             // vs -> v1 (coeff vv[u,i]*sh0)
          for (int p = t; p < 768; p += 256){
            int e = p/12, r = p - e*12, w1 = r/3, i = r - w1*3;
            const float* wr = sWT + e*WTP + w1;
            float a = 0.f;
#pragma unroll
            for (int du = 0; du < 16; du++) a += sVV[e*VVP+du*3+i]*wr[du*4];
            sV1[e*V1P + h*12 + w1*3 + i] += a*sSH[e*4];
          }
        }
        off0 += 64;
        if (off0 == 576){ off0 = 0; h++; }
      }
      // epilogue->next-tile ordering handled by the top-of-tile sync
    }
    __syncthreads();   // all epilogues done before logits/outputs
  }

  // write v-set outputs (accumulators hold set 1 now)
#pragma unroll
  for (int ph = 0; ph < 8; ph++){
    int p = t + ph*256;
    int e = p >> 5, cc = p & 31;
    int eg = eg0 + e;
    if (eg < E) d_v0e[(size_t)eg*32 + cc] = sO0[e*O0P + cc]*RFANf;
  }
  for (int p = t; p < 3072; p += 256){
    int e = p/48, r = p - e*48;
    int h = r/12, q = r - h*12, w1 = q/3, i = q - w1*3;
    int eg = eg0 + e;
    if (eg < E)
      d_v1e[(size_t)eg*48 + r] =
        (sS1[e*S1P + h*4 + w1]*sSH[e*4+1+i] + sV1[e*V1P + r])*RFANf;
  }
}

__global__ void k_ex(const int* __restrict__ ei, int E){
  int t = blockIdx.x*blockDim.x+threadIdx.x;
  if (t >= E*4) return;
  int e = t >> 2, h = t & 3;
  int dst = ei[E + e];
  float ex = expf(d_logits[t] - d_segmax[dst*4+h]);
  d_exb[t] = ex;
  atomicAdd(d_denom + dst*4 + h, ex);
}

__global__ void k_agg(const int* __restrict__ ei, int E){
  int t = blockIdx.x*blockDim.x+threadIdx.x;
  if (t >= E*80) return;
  int e = t/80, r = t - e*80;
  int dst = ei[E + e];
  if (r < 32){
    int h = r >> 3;
    float alpha = d_exb[e*4+h]/(d_denom[dst*4+h] + 1e-12f);
    atomicAdd(d_agg0 + dst*32 + r, alpha*d_v0e[(size_t)e*32 + r]);
  } else {
    int r2 = r - 32, h = r2/12;
    float alpha = d_exb[e*4+h]/(d_denom[dst*4+h] + 1e-12f);
    atomicAdd(d_agg1 + dst*48 + r2, alpha*d_v1e[(size_t)e*48 + r2]);
  }
}

__global__ void k_node(const float* __restrict__ nf,
    const float* __restrict__ Wo0, const float* __restrict__ Wo1,
    const float* __restrict__ Wf10, const float* __restrict__ Wf11,
    const float* __restrict__ Wf20, const float* __restrict__ Wf21,
    float* __restrict__ out, int N)
{
  __shared__ float sx0[32], sx1[48], sa0[64], sa1[48];
  int n = blockIdx.x, t = threadIdx.x;
  if (t < 32){
    float acc = 0.f;
#pragma unroll
    for (int u = 0; u < 32; u++) acc += d_agg0[n*32+u]*Wo0[u*32+t];
    sx0[t] = nf[(size_t)n*80 + t] + acc*RS32f;
  } else if (t < 80){
    int r = t-32, w = r/3, i = r - w*3;
    float acc = 0.f;
#pragma unroll
    for (int u = 0; u < 16; u++) acc += d_agg1[n*48+u*3+i]*Wo1[u*16+w];
    sx1[r] = nf[(size_t)n*80 + 32 + r] + acc*0.25f;
  }
  __syncthreads();
  if (t < 64){
    float acc = 0.f;
#pragma unroll
    for (int u = 0; u < 32; u++) acc += sx0[u]*Wf10[u*64+t];
    float a = acc*RS32f;
    sa0[t] = a/(1.f+expf(-a));
  } else if (t < 112){
    int r = t-64, w = r/3, i = r - w*3;
    float acc = 0.f;
#pragma unroll
    for (int u = 0; u < 16; u++) acc += sx1[u*3+i]*Wf11[u*16+w];
    sa1[r] = acc*0.25f;
  }
  __syncthreads();
  if (t < 16){
    float x = sa1[t*3], y = sa1[t*3+1], z = sa1[t*3+2];
    float nm = sqrtf(x*x+y*y+z*z);
    float g = (nm < 1e-8f) ? 0.f : (nm/(1.f+expf(-nm)))/nm;
    sa1[t*3] = x*g; sa1[t*3+1] = y*g; sa1[t*3+2] = z*g;
  }
  __syncthreads();
  if (t < 32){
    float acc = 0.f;
#pragma unroll
    for (int u = 0; u < 64; u++) acc += sa0[u]*Wf20[u*32+t];
    out[(size_t)n*80 + t] = sx0[t] + acc*0.125f;
  } else if (t < 80){
    int r = t-32, w = r/3, i = r - w*3;
    float acc = 0.f;
#pragma unroll
    for (int u = 0; u < 16; u++) acc += sa1[u*3+i]*Wf21[u*16+w];
    out[(size_t)n*80 + t] = sx1[r] + acc*0.25f;
  }
}

extern "C" void kernel_launch(void* const* d_in, const int* in_sizes, int n_in,
                              void* d_out, int out_size){
  const float* nf   = (const float*)d_in[0];
  const int*   ei   = (const int*)  d_in[1];
  const float* esh  = (const float*)d_in[2];
  const float* emb  = (const float*)d_in[3];
  const float* Wq0  = (const float*)d_in[4];
  const float* Wq1  = (const float*)d_in[5];
  const float* Wk1  = (const float*)d_in[6];
  const float* bk1  = (const float*)d_in[7];
  const float* Wk2  = (const float*)d_in[8];
  const float* bk2  = (const float*)d_in[9];
  const float* Wv1  = (const float*)d_in[10];
  const float* bv1  = (const float*)d_in[11];
  const float* Wv2  = (const float*)d_in[12];
  const float* bv2  = (const float*)d_in[13];
  const float* Wd0  = (const float*)d_in[14];
  const float* Wd1  = (const float*)d_in[15];
  const float* Wo0  = (const float*)d_in[16];
  const float* Wo1  = (const float*)d_in[17];
  const float* Wf10 = (const float*)d_in[18];
  const float* Wf11 = (const float*)d_in[19];
  const float* Wf20 = (const float*)d_in[20];
  const float* Wf21 = (const float*)d_in[21];
  float* out = (float*)d_out;

  int N = in_sizes[0]/80;
  int E = in_sizes[1]/2;

  static int inited = 0;
  if (!inited){
    cudaFuncSetAttribute(k_edge, cudaFuncAttributeMaxDynamicSharedMemorySize, SMEM_BYTES);
    inited = 1;
  }
  int nT = (E + 63)/64;

  k_prep<<<(2*32*2304+255)/256, 256>>>(Wk2, Wv2);
  k_init<<<(N*48+255)/256, 256>>>(N);
  k_q<<<(N*80+255)/256, 256>>>(nf, Wq0, Wq1, N);
  k_edge<<<nT, 256, SMEM_BYTES>>>(nf, ei, esh, emb,
      Wk1, bk1, bk2, Wv1, bv1, bv2, Wd0, Wd1, N, E);
  k_ex<<<(E*4+255)/256, 256>>>(ei, E);
  k_agg<<<(E*80+255)/256, 256>>>(ei, E);
  k_node<<<N, 128>>>(nf, Wo0, Wo1, Wf10, Wf11, Wf20, Wf21, out, N);
}

// round 16
// speedup vs baseline: 1.6522x; 1.0067x over previous
#include <cuda_runtime.h>
#include <cuda_bf16.h>
#include <math.h>
#include <stdint.h>

#define MAX_N 2048
#define MAX_E 32768
#define RFANf   0.14433756729740643f  // 1/sqrt(48)
#define RSQRT3f 0.57735026918962576f
#define RS32f   0.17677669529663687f  // 1/sqrt(32)

__device__ float d_q0g[MAX_N*32];
__device__ float d_q1g[MAX_N*48];
__device__ float d_v0e[(size_t)MAX_E*32];
__device__ float d_v1e[(size_t)MAX_E*48];
__device__ float d_logits[MAX_E*4];
__device__ float d_exb[MAX_E*4];
__device__ float d_segmax[MAX_N*4];
__device__ float d_denom[MAX_N*4];
__device__ float d_agg0[MAX_N*32];
__device__ float d_agg1[MAX_N*48];
// W2 bf16 hi/lo, k-pair-adjacent layout:
// row = set*32 + (lo?16:0) + (ks*4+c), 4608 words/row, word index = j*2 + w
__device__ unsigned int d_W2p[128*2304];

__device__ __forceinline__ void atomicMaxF(float* a, float v){
  if (v >= 0.f) atomicMax((int*)a, __float_as_int(v));
  else atomicMin((unsigned int*)a, __float_as_uint(v));
}
__device__ __forceinline__ unsigned packbf(float x, float y){
  unsigned short ux = __bfloat16_as_ushort(__float2bfloat16(x));
  unsigned short uy = __bfloat16_as_ushort(__float2bfloat16(y));
  return ((unsigned)uy << 16) | (unsigned)ux;
}

__global__ void k_prep(const float* __restrict__ W2k, const float* __restrict__ W2v){
  int t = blockIdx.x*blockDim.x + threadIdx.x;
  if (t >= 2*32*2304) return;
  int s  = t / (32*2304);
  int r  = t - s*32*2304;
  int kp = r / 2304;
  int j  = r - kp*2304;
  const float* W = s ? W2v : W2k;
  float a0 = W[(2*kp)*2304 + j];
  float a1 = W[(2*kp+1)*2304 + j];
  __nv_bfloat16 h0 = __float2bfloat16(a0);
  __nv_bfloat16 h1 = __float2bfloat16(a1);
  unsigned hi = ((unsigned)__bfloat16_as_ushort(h1)<<16) | __bfloat16_as_ushort(h0);
  unsigned lo = packbf(a0 - __bfloat162float(h0), a1 - __bfloat162float(h1));
  int ks = kp >> 3, rem = kp & 7;
  int w = rem >> 2, c = rem & 3;
  int p = (ks<<2) + c;
  d_W2p[(size_t)(s*32 + p)*4608 + j*2 + w]      = hi;
  d_W2p[(size_t)(s*32 + 16 + p)*4608 + j*2 + w] = lo;
}

__global__ void k_init(int N){
  int t = blockIdx.x*blockDim.x+threadIdx.x;
  if (t < N*4){ d_segmax[t] = -10.0f; d_denom[t] = 0.0f; }
  if (t < N*32) d_agg0[t] = 0.0f;
  if (t < N*48) d_agg1[t] = 0.0f;
}

__global__ void k_q(const float* __restrict__ nf, const float* __restrict__ Wq0,
                    const float* __restrict__ Wq1, int N){
  int t = blockIdx.x*blockDim.x+threadIdx.x;
  if (t >= N*80) return;
  int n = t/80, r = t - n*80;
  if (r < 32){
    int h = r>>3, w = r&7;
    const float* s = nf + (size_t)n*80;
    float acc = 0.f;
#pragma unroll
    for (int u = 0; u < 32; u++) acc += s[u]*Wq0[h*256+u*8+w];
    d_q0g[n*32+r] = acc*RS32f;
  } else {
    int rr = r-32, h = rr/12, q = rr - h*12, w = q/3, i = q - w*3;
    const float* v = nf + (size_t)n*80 + 32;
    float acc = 0.f;
#pragma unroll
    for (int u = 0; u < 16; u++) acc += v[u*3+i]*Wq1[h*64+u*4+w];
    d_q1g[n*48+rr] = acc*0.25f;
  }
}

// ---- smem layout (32-bit words), 64 edges/CTA, 2 CTAs/SM ----
#define OFF_B0   0        // 32 rows * 136
#define OFF_B1   4352     // 32 rows * 136 ; setup alias: W1(1088)
#define BRS      136
#define BBUFW    4352
#define OFF_WT   8704     // 64*72 ; setup alias: sA (64*68 = 4352)
#define WTP      72
#define ARS      68
#define OFF_O0   13312    // 64*40
#define O0P      40
#define OFF_S1   15872    // 64*20
#define S1P      20
#define OFF_V1   17152    // 64*48
#define V1P      48
#define OFF_SS   20224    // 64*36
#define SSP      36
#define OFF_VV   22528    // 64*48
#define VVP      48
#define OFF_CVV  25600    // 64*16
#define CVP      16
#define OFF_SH   26624    // 64*4
#define OFF_EMB  26880    // 64*16
#define OFF_IDX  27904    // 128
#define SMEM_WORDS 28032
#define SMEM_BYTES (SMEM_WORDS*4)   // 112128

__device__ __forceinline__ void cp16(void* dst, const void* src){
  uint32_t a = (uint32_t)__cvta_generic_to_shared(dst);
  asm volatile("cp.async.cg.shared.global [%0], [%1], 16;" :: "r"(a), "l"(src));
}
__device__ __forceinline__ void mma16(float* c, unsigned a0, unsigned a1, unsigned a2, unsigned a3,
                                      unsigned b0, unsigned b1){
  asm volatile(
    "mma.sync.aligned.m16n8k16.row.col.f32.bf16.bf16.f32 "
    "{%0,%1,%2,%3},{%4,%5,%6,%7},{%8,%9},{%0,%1,%2,%3};"
    : "+f"(c[0]), "+f"(c[1]), "+f"(c[2]), "+f"(c[3])
    : "r"(a0), "r"(a1), "r"(a2), "r"(a3), "r"(b0), "r"(b1));
}

__global__ void __launch_bounds__(256,2) k_edge(
    const float* __restrict__ nf, const int* __restrict__ ei,
    const float* __restrict__ esh, const float* __restrict__ emb,
    const float* __restrict__ W1k, const float* __restrict__ b1k,
    const float* __restrict__ b2k,
    const float* __restrict__ W1v, const float* __restrict__ b1v,
    const float* __restrict__ b2v,
    const float* __restrict__ Wd0, const float* __restrict__ Wd1,
    int N, int E)
{
  extern __shared__ float sm[];
  unsigned* sB  = (unsigned*)(sm + OFF_B0);       // two 4352-word buffers
  float* sW1  = sm + OFF_B1;                      // setup alias in buf1
  unsigned* sA  = (unsigned*)(sm + OFF_WT);       // setup alias in WT
  float* sWT  = sm + OFF_WT;
  float* sO0  = sm + OFF_O0;
  float* sS1  = sm + OFF_S1;
  float* sV1  = sm + OFF_V1;
  float* sSS  = sm + OFF_SS;
  float* sVV  = sm + OFF_VV;
  float* sCVV = sm + OFF_CVV;
  float* sSH  = sm + OFF_SH;
  float* sEmb = sm + OFF_EMB;
  int*   sIdx = (int*)(sm + OFF_IDX);

  const int t    = threadIdx.x;
  const int lane = t & 31;
  const int wid  = t >> 5;
  const int wm   = wid >> 2, wn = wid & 3;   // warp: m32 (wm) x n16 (wn)
  const int g    = lane >> 2, c = lane & 3;
  const int row0 = (wm << 5) + g;
  const int row1 = row0 + 16;

  const int eg0 = blockIdx.x << 6;           // one 64-edge group per block

  // prefetch B(set0, it0) into buf0 — slack = entire group setup
  {
    int r = t >> 3, ch = t & 7;
    const unsigned* gsrc = d_W2p + (size_t)r*4608;
#pragma unroll
    for (int q = 0; q < 4; q++){
      int jw = (ch + (q<<3)) << 2;
      cp16(sB + r*BRS + jw, gsrc + jw);
    }
    asm volatile("cp.async.commit_group;");
  }

  if (t < 128){
    int e = t & 63, which = t >> 6;
    int eg = eg0 + e;
    sIdx[t] = (eg < E) ? ei[(size_t)which*E + eg] : 0;
  }
  {
    int e = t >> 2, cc = t & 3;
    int eg = eg0 + e;
    bool val = eg < E;
    sSH[e*4+cc] = val ? esh[(size_t)eg*4+cc] : 0.f;
    float4 z = make_float4(0,0,0,0);
    float4 d = val ? *(const float4*)(emb + (size_t)eg*16 + cc*4) : z;
    *(float4*)(sEmb + e*16 + cc*4) = d;
  }
  __syncthreads();

  // gather src node features (20 float4 per edge), padded strides
#pragma unroll
  for (int ph = 0; ph < 4; ph++){
    int p = t + ph*256;
    int e = p >> 4, f4 = p & 15;
    const float4* row = (const float4*)(nf + (size_t)sIdx[e]*80);
    float4 d = row[f4];
    if (f4 < 8) *((float4*)(sSS + e*SSP) + f4) = d;
    else        *((float4*)(sVV + e*VVP) + (f4-8)) = d;
  }
  {
    int e = t >> 2, f4 = 16 + (t & 3);
    const float4* row = (const float4*)(nf + (size_t)sIdx[e]*80);
    *((float4*)(sVV + e*VVP) + (f4-8)) = row[f4];
  }
  __syncthreads();

  // cvv
#pragma unroll
  for (int ph = 0; ph < 4; ph++){
    int p = t + ph*256;
    int e = p >> 4, u = p & 15;
    const float* vv = sVV + e*VVP + u*3;
    sCVV[e*CVP + u] = (vv[0]*sSH[e*4+1] + vv[1]*sSH[e*4+2] + vv[2]*sSH[e*4+3]) * RSQRT3f;
  }
  __syncthreads();

  // ---- two sets, sequential ----
#pragma unroll 1
  for (int s = 0; s < 2; s++){
    if (s == 1){
      // logits from k-set accumulators (before re-zero)
      __syncthreads();
      {
        int e = t >> 2, h = t & 3;
        int eg = eg0 + e;
        int dst = sIdx[64 + e];
        float k0r[8];
#pragma unroll
        for (int w = 0; w < 8; w++) k0r[w] = sO0[e*O0P + h*8 + w]*RFANf;
        const float* q0 = d_q0g + dst*32 + h*8;
        float l0 = 0.f;
#pragma unroll
        for (int v = 0; v < 8; v++){
          float tv = 0.f;
#pragma unroll
          for (int u = 0; u < 8; u++) tv += q0[u]*Wd0[u*8+v];
          l0 += tv*k0r[v];
        }
        float k1r[12];
#pragma unroll
        for (int w1 = 0; w1 < 4; w1++)
#pragma unroll
          for (int i = 0; i < 3; i++)
            k1r[w1*3+i] = (sS1[e*S1P+h*4+w1]*sSH[e*4+1+i] + sV1[e*V1P+h*12+w1*3+i])*RFANf;
        const float* q1 = d_q1g + dst*48 + h*12;
        float l1 = 0.f;
#pragma unroll
        for (int u = 0; u < 4; u++)
#pragma unroll
          for (int v = 0; v < 4; v++){
            float d3 = q1[u*3]*k1r[v*3] + q1[u*3+1]*k1r[v*3+1] + q1[u*3+2]*k1r[v*3+2];
            l1 += Wd1[u*4 + v]*d3;
          }
        float lg = (l0 + l1*RSQRT3f)*0.025f;
        lg = fminf(fmaxf(lg, -10.f), 10.f);
        if (eg < E){
          d_logits[eg*4 + h] = lg;
          atomicMaxF(d_segmax + dst*4 + h, lg);
        }
      }
      __syncthreads();

      // prefetch B(set1, it0) into buf0 — slack = entire set-1 setup
      {
        int r = t >> 3, ch = t & 7;
        const unsigned* gsrc = d_W2p + (size_t)(32 + r)*4608;
#pragma unroll
        for (int q = 0; q < 4; q++){
          int jw = (ch + (q<<3)) << 2;
          cp16(sB + r*BRS + jw, gsrc + jw);
        }
        asm volatile("cp.async.commit_group;");
      }
    }

    // stage W1/b1 into buf1 alias; zero accumulators
    {
      const float* W1s = s ? W1v : W1k;
      const float* b1s = s ? b1v : b1k;
      for (int i = t; i < 1024; i += 256) sW1[i] = W1s[i];
      if (t < 64) sW1[1024+t] = b1s[t];
      for (int i = t; i < 1728; i += 256) *(float4*)(sO0 + i*4) = make_float4(0,0,0,0);
    }
    __syncthreads();

    // hE for this set -> sA (bf16 hi/lo pairs), aliased in WT
    {
      int e = t >> 2, kq = (t & 3) << 4;
      float v[16];
#pragma unroll
      for (int kk = 0; kk < 16; kk++){
        int k = kq + kk;
        float a = sW1[1024 + k];
#pragma unroll
        for (int b = 0; b < 16; b++) a += sEmb[e*16+b]*sW1[b*64+k];
        v[kk] = a/(1.f+expf(-a));
      }
      unsigned* arow = sA + e*ARS + (kq>>1);
#pragma unroll
      for (int p = 0; p < 8; p++){
        float x = v[2*p], y = v[2*p+1];
        __nv_bfloat16 hx = __float2bfloat16(x), hy = __float2bfloat16(y);
        arow[p]      = ((unsigned)__bfloat16_as_ushort(hy)<<16) | __bfloat16_as_ushort(hx);
        arow[32 + p] = packbf(x - __bfloat162float(hx), y - __bfloat162float(hy));
      }
    }
    __syncthreads();

    // hoist A fragments (two m16 groups) into registers for the whole set
    unsigned ah0[4][4], al0[4][4], ah1[4][4], al1[4][4];
    {
      const unsigned* p0  = sA + row0*ARS;
      const unsigned* p08 = sA + (row0+8)*ARS;
      const unsigned* p1  = sA + row1*ARS;
      const unsigned* p18 = sA + (row1+8)*ARS;
#pragma unroll
      for (int ks = 0; ks < 4; ks++){
        int kb = ks*8 + c;
        ah0[ks][0] = p0[kb];     ah0[ks][1] = p08[kb];
        ah0[ks][2] = p0[kb+4];   ah0[ks][3] = p08[kb+4];
        al0[ks][0] = p0[32+kb];  al0[ks][1] = p08[32+kb];
        al0[ks][2] = p0[32+kb+4];al0[ks][3] = p08[32+kb+4];
        ah1[ks][0] = p1[kb];     ah1[ks][1] = p18[kb];
        ah1[ks][2] = p1[kb+4];   ah1[ks][3] = p18[kb+4];
        al1[ks][0] = p1[32+kb];  al1[ks][1] = p18[32+kb];
        al1[ks][2] = p1[32+kb+4];al1[ks][3] = p18[32+kb+4];
      }
    }
    __syncthreads();   // sA dead; sWT writable

    // bias pipeline: preload tile 0's bias into registers
    const float* b2p = s ? b2v : b2k;
    float2 bb0 = *(const float2*)(b2p + (wn<<4) + 2*c);
    float2 bb1 = *(const float2*)(b2p + (wn<<4) + 8 + 2*c);

    // ---- 36 tiles of 64 j, double-buffered B ----
    int h = 0, off0 = 0;
    for (int it = 0; it < 36; it++){

      asm volatile("cp.async.wait_group 0;");
      __syncthreads();   // B(it) visible; epilogue(it-1) done (sWT writable)

      // prefetch B(it+1) into the other buffer (full-tile slack)
      if (it + 1 < 36){
        int j02 = (it+1) << 6;
        unsigned* db = sB + ((it+1)&1)*BBUFW;
        int r = t >> 3, ch = t & 7;
        const unsigned* gsrc = d_W2p + (size_t)(s*32 + r)*4608 + j02*2;
#pragma unroll
        for (int q = 0; q < 4; q++){
          int jw = (ch + (q<<3)) << 2;
          cp16(db + r*BRS + jw, gsrc + jw);
        }
        asm volatile("cp.async.commit_group;");
      }

      const unsigned* sBb = sB + (it&1)*BBUFW;

      // acc init from pipelined bias registers
      float acc0[2][4], acc1[2][4];
      acc0[0][0]=bb0.x; acc0[0][1]=bb0.y; acc0[0][2]=bb0.x; acc0[0][3]=bb0.y;
      acc0[1][0]=bb1.x; acc0[1][1]=bb1.y; acc0[1][2]=bb1.x; acc0[1][3]=bb1.y;
      acc1[0][0]=bb0.x; acc1[0][1]=bb0.y; acc1[0][2]=bb0.x; acc1[0][3]=bb0.y;
      acc1[1][0]=bb1.x; acc1[1][1]=bb1.y; acc1[1][2]=bb1.x; acc1[1][3]=bb1.y;
      // load next tile's bias (consumed next iteration; full-tile slack)
      if (it + 1 < 36){
        int j02 = (it+1) << 6;
        bb0 = *(const float2*)(b2p + j02 + (wn<<4) + 2*c);
        bb1 = *(const float2*)(b2p + j02 + (wn<<4) + 8 + 2*c);
      }

#pragma unroll
      for (int ks = 0; ks < 4; ks++){
#pragma unroll
        for (int nt = 0; nt < 2; nt++){
          const unsigned long long* bQ = (const unsigned long long*)
            (sBb + ((ks<<2) + c)*BRS + (((wn<<4) + (nt<<3) + g)<<1));
          unsigned long long bh = bQ[0];
          unsigned long long bl = bQ[16*BRS/2];
          unsigned bh0 = (unsigned)bh, bh1 = (unsigned)(bh>>32);
          unsigned bl0 = (unsigned)bl, bl1 = (unsigned)(bl>>32);
          mma16(acc0[nt], ah0[ks][0],ah0[ks][1],ah0[ks][2],ah0[ks][3], bh0,bh1);
          mma16(acc0[nt], al0[ks][0],al0[ks][1],al0[ks][2],al0[ks][3], bh0,bh1);
          mma16(acc0[nt], ah0[ks][0],ah0[ks][1],ah0[ks][2],ah0[ks][3], bl0,bl1);
          mma16(acc1[nt], ah1[ks][0],ah1[ks][1],ah1[ks][2],ah1[ks][3], bh0,bh1);
          mma16(acc1[nt], al1[ks][0],al1[ks][1],al1[ks][2],al1[ks][3], bh0,bh1);
          mma16(acc1[nt], ah1[ks][0],ah1[ks][1],ah1[ks][2],ah1[ks][3], bl0,bl1);
        }
      }
      // stage w tile
#pragma unroll
      for (int nt = 0; nt < 2; nt++){
        int jl = (wn<<4) + (nt<<3) + 2*c;
        *(float2*)(sWT + row0*WTP + jl)      = make_float2(acc0[nt][0], acc0[nt][1]);
        *(float2*)(sWT + (row0+8)*WTP + jl)  = make_float2(acc0[nt][2], acc0[nt][3]);
        *(float2*)(sWT + row1*WTP + jl)      = make_float2(acc1[nt][0], acc1[nt][1]);
        *(float2*)(sWT + (row1+8)*WTP + jl)  = make_float2(acc1[nt][2], acc1[nt][3]);
      }
      __syncthreads();   // sWT staged; B(it) consumed

      // epilogue: contract this 64-j block (h/off0 loop-carried; vectorized coeffs)
      {
        if (off0 < 256){                     // ss -> out0 (coeff ss[u]*sh0)
          int u0 = off0 >> 3;
#pragma unroll
          for (int ph = 0; ph < 2; ph++){
            int p = t + ph*256;
            int e = p >> 3, ow = p & 7;
            const float* wr = sWT + e*WTP + ow;
            float4 s0 = *(const float4*)(sSS + e*SSP + u0);
            float4 s1 = *(const float4*)(sSS + e*SSP + u0 + 4);
            float a = s0.x*wr[0] + s0.y*wr[8] + s0.z*wr[16] + s0.w*wr[24]
                    + s1.x*wr[32] + s1.y*wr[40] + s1.z*wr[48] + s1.w*wr[56];
            sO0[e*O0P + h*8 + ow] += a*sSH[e*4];
          }
        } else if (off0 < 384){              // vv -> out0 (coeff cvv[u])
          int u0 = (off0-256) >> 3;
#pragma unroll
          for (int ph = 0; ph < 2; ph++){
            int p = t + ph*256;
            int e = p >> 3, ow = p & 7;
            const float* wr = sWT + e*WTP + ow;
            float4 s0 = *(const float4*)(sCVV + e*CVP + u0);
            float4 s1 = *(const float4*)(sCVV + e*CVP + u0 + 4);
            float a = s0.x*wr[0] + s0.y*wr[8] + s0.z*wr[16] + s0.w*wr[24]
                    + s1.x*wr[32] + s1.y*wr[40] + s1.z*wr[48] + s1.w*wr[56];
            sO0[e*O0P + h*8 + ow] += a;
          }
        } else if (off0 < 512){              // sv -> s1 (coeff ss[u])
          int u0 = (off0-384) >> 2;
          int e = t >> 2, w1 = t & 3;
          const float* wr = sWT + e*WTP + w1;
          float a = 0.f;
#pragma unroll
          for (int q4 = 0; q4 < 4; q4++){
            float4 sv = *(const float4*)(sSS + e*SSP + u0 + q4*4);
            a += sv.x*wr[q4*16] + sv.y*wr[q4*16+4] + sv.z*wr[q4*16+8] + sv.w*wr[q4*16+12];
          }
          sS1[e*S1P + h*4 + w1] += a;
        } else {                             // vs -> v1 (coeff vv[u,i]*sh0)
          for (int p = t; p < 768; p += 256){
            int e = p/12, r = p - e*12, w1 = r/3, i = r - w1*3;
            const float* wr = sWT + e*WTP + w1;
            float a = 0.f;
#pragma unroll
            for (int du = 0; du < 16; du++) a += sVV[e*VVP+du*3+i]*wr[du*4];
            sV1[e*V1P + h*12 + w1*3 + i] += a*sSH[e*4];
          }
        }
        off0 += 64;
        if (off0 == 576){ off0 = 0; h++; }
      }
      // epilogue->next-tile ordering handled by the top-of-tile sync
    }
    __syncthreads();   // all epilogues done before logits/outputs
  }

  // write v-set outputs (accumulators hold set 1 now)
#pragma unroll
  for (int ph = 0; ph < 8; ph++){
    int p = t + ph*256;
    int e = p >> 5, cc = p & 31;
    int eg = eg0 + e;
    if (eg < E) d_v0e[(size_t)eg*32 + cc] = sO0[e*O0P + cc]*RFANf;
  }
  for (int p = t; p < 3072; p += 256){
    int e = p/48, r = p - e*48;
    int h = r/12, q = r - h*12, w1 = q/3, i = q - w1*3;
    int eg = eg0 + e;
    if (eg < E)
      d_v1e[(size_t)eg*48 + r] =
        (sS1[e*S1P + h*4 + w1]*sSH[e*4+1+i] + sV1[e*V1P + r])*RFANf;
  }
}

__global__ void k_ex(const int* __restrict__ ei, int E){
  int t = blockIdx.x*blockDim.x+threadIdx.x;
  if (t >= E*4) return;
  int e = t >> 2, h = t & 3;
  int dst = ei[E + e];
  float ex = expf(d_logits[t] - d_segmax[dst*4+h]);
  d_exb[t] = ex;
  atomicAdd(d_denom + dst*4 + h, ex);
}

__global__ void k_agg(const int* __restrict__ ei, int E){
  int t = blockIdx.x*blockDim.x+threadIdx.x;
  if (t >= E*80) return;
  int e = t/80, r = t - e*80;
  int dst = ei[E + e];
  if (r < 32){
    int h = r >> 3;
    float alpha = d_exb[e*4+h]/(d_denom[dst*4+h] + 1e-12f);
    atomicAdd(d_agg0 + dst*32 + r, alpha*d_v0e[(size_t)e*32 + r]);
  } else {
    int r2 = r - 32, h = r2/12;
    float alpha = d_exb[e*4+h]/(d_denom[dst*4+h] + 1e-12f);
    atomicAdd(d_agg1 + dst*48 + r2, alpha*d_v1e[(size_t)e*48 + r2]);
  }
}

__global__ void k_node(const float* __restrict__ nf,
    const float* __restrict__ Wo0, const float* __restrict__ Wo1,
    const float* __restrict__ Wf10, const float* __restrict__ Wf11,
    const float* __restrict__ Wf20, const float* __restrict__ Wf21,
    float* __restrict__ out, int N)
{
  __shared__ float sx0[32], sx1[48], sa0[64], sa1[48];
  int n = blockIdx.x, t = threadIdx.x;
  if (t < 32){
    float acc = 0.f;
#pragma unroll
    for (int u = 0; u < 32; u++) acc += d_agg0[n*32+u]*Wo0[u*32+t];
    sx0[t] = nf[(size_t)n*80 + t] + acc*RS32f;
  } else if (t < 80){
    int r = t-32, w = r/3, i = r - w*3;
    float acc = 0.f;
#pragma unroll
    for (int u = 0; u < 16; u++) acc += d_agg1[n*48+u*3+i]*Wo1[u*16+w];
    sx1[r] = nf[(size_t)n*80 + 32 + r] + acc*0.25f;
  }
  __syncthreads();
  if (t < 64){
    float acc = 0.f;
#pragma unroll
    for (int u = 0; u < 32; u++) acc += sx0[u]*Wf10[u*64+t];
    float a = acc*RS32f;
    sa0[t] = a/(1.f+expf(-a));
  } else if (t < 112){
    int r = t-64, w = r/3, i = r - w*3;
    float acc = 0.f;
#pragma unroll
    for (int u = 0; u < 16; u++) acc += sx1[u*3+i]*Wf11[u*16+w];
    sa1[r] = acc*0.25f;
  }
  __syncthreads();
  if (t < 16){
    float x = sa1[t*3], y = sa1[t*3+1], z = sa1[t*3+2];
    float nm = sqrtf(x*x+y*y+z*z);
    float g = (nm < 1e-8f) ? 0.f : (nm/(1.f+expf(-nm)))/nm;
    sa1[t*3] = x*g; sa1[t*3+1] = y*g; sa1[t*3+2] = z*g;
  }
  __syncthreads();
  if (t < 32){
    float acc = 0.f;
#pragma unroll
    for (int u = 0; u < 64; u++) acc += sa0[u]*Wf20[u*32+t];
    out[(size_t)n*80 + t] = sx0[t] + acc*0.125f;
  } else if (t < 80){
    int r = t-32, w = r/3, i = r - w*3;
    float acc = 0.f;
#pragma unroll
    for (int u = 0; u < 16; u++) acc += sa1[u*3+i]*Wf21[u*16+w];
    out[(size_t)n*80 + t] = sx1[r] + acc*0.25f;
  }
}

extern "C" void kernel_launch(void* const* d_in, const int* in_sizes, int n_in,
                              void* d_out, int out_size){
  const float* nf   = (const float*)d_in[0];
  const int*   ei   = (const int*)  d_in[1];
  const float* esh  = (const float*)d_in[2];
  const float* emb  = (const float*)d_in[3];
  const float* Wq0  = (const float*)d_in[4];
  const float* Wq1  = (const float*)d_in[5];
  const float* Wk1  = (const float*)d_in[6];
  const float* bk1  = (const float*)d_in[7];
  const float* Wk2  = (const float*)d_in[8];
  const float* bk2  = (const float*)d_in[9];
  const float* Wv1  = (const float*)d_in[10];
  const float* bv1  = (const float*)d_in[11];
  const float* Wv2  = (const float*)d_in[12];
  const float* bv2  = (const float*)d_in[13];
  const float* Wd0  = (const float*)d_in[14];
  const float* Wd1  = (const float*)d_in[15];
  const float* Wo0  = (const float*)d_in[16];
  const float* Wo1  = (const float*)d_in[17];
  const float* Wf10 = (const float*)d_in[18];
  const float* Wf11 = (const float*)d_in[19];
  const float* Wf20 = (const float*)d_in[20];
  const float* Wf21 = (const float*)d_in[21];
  float* out = (float*)d_out;

  int N = in_sizes[0]/80;
  int E = in_sizes[1]/2;

  static int inited = 0;
  if (!inited){
    cudaFuncSetAttribute(k_edge, cudaFuncAttributeMaxDynamicSharedMemorySize, SMEM_BYTES);
    inited = 1;
  }
  int nT = (E + 63)/64;

  k_prep<<<(2*32*2304+255)/256, 256>>>(Wk2, Wv2);
  k_init<<<(N*48+255)/256, 256>>>(N);
  k_q<<<(N*80+255)/256, 256>>>(nf, Wq0, Wq1, N);
  k_edge<<<nT, 256, SMEM_BYTES>>>(nf, ei, esh, emb,
      Wk1, bk1, bk2, Wv1, bv1, bv2, Wd0, Wd1, N, E);
  k_ex<<<(E*4+255)/256, 256>>>(ei, E);
  k_agg<<<(E*80+255)/256, 256>>>(ei, E);
  k_node<<<N, 128>>>(nf, Wo0, Wo1, Wf10, Wf11, Wf20, Wf21, out, N);
}